// round 1
// baseline (speedup 1.0000x reference)
#include <cuda_runtime.h>

#define N_TOK 8192
#define DIM   1024
#define NEXP  8
#define CAP   1024

// ---------------- scratch (device globals; no allocation allowed) ----------
__device__ float g_expert_in[(size_t)NEXP * CAP * DIM];  // 32 MB
__device__ float g_h[(size_t)NEXP * CAP * DIM];          // 32 MB
__device__ float g_eo[(size_t)NEXP * CAP * DIM];         // 32 MB
__device__ int   g_idx[N_TOK];
__device__ float g_gate[N_TOK];
__device__ int   g_comb[N_TOK];     // e*CAP + pos (1-based), or -1 if dropped
__device__ int   g_tok[NEXP * CAP]; // token id per (expert,slot), -1 if empty

// ---------------- router: one warp per token --------------------------------
__global__ void router_kernel(const float* __restrict__ x,
                              const float* __restrict__ Wr,
                              const float* __restrict__ br) {
    int gwarp = (blockIdx.x * blockDim.x + threadIdx.x) >> 5;
    int lane  = threadIdx.x & 31;
    if (gwarp >= N_TOK) return;
    const float* xr = x + (size_t)gwarp * DIM;
    float acc[NEXP];
#pragma unroll
    for (int e = 0; e < NEXP; e++) acc[e] = 0.f;
    for (int d = lane; d < DIM; d += 32) {
        float xv = xr[d];
        const float* w = Wr + d * NEXP;
#pragma unroll
        for (int e = 0; e < NEXP; e++) acc[e] += xv * w[e];
    }
#pragma unroll
    for (int o = 16; o > 0; o >>= 1)
#pragma unroll
        for (int e = 0; e < NEXP; e++)
            acc[e] += __shfl_xor_sync(0xffffffffu, acc[e], o);
    if (lane == 0) {
        float m = -1e30f; int ai = 0;
#pragma unroll
        for (int e = 0; e < NEXP; e++) {
            acc[e] += br[e];
            if (acc[e] > m) { m = acc[e]; ai = e; }  // strict > keeps first (jnp.argmax)
        }
        float s = 0.f;
#pragma unroll
        for (int e = 0; e < NEXP; e++) s += expf(acc[e] - m);
        g_idx[gwarp]  = ai;
        g_gate[gwarp] = 1.f / s;   // max prob
    }
}

// ---------------- init token table ------------------------------------------
__global__ void init_tok_kernel() {
    int i = blockIdx.x * blockDim.x + threadIdx.x;
    if (i < NEXP * CAP) g_tok[i] = -1;
}

// ---------------- order-preserving per-expert position scan -----------------
// One block, 1024 threads, 8 chunks. 8 expert counters packed as 2 x (4x16-bit)
// words so a single Hillis-Steele scan handles all experts at once.
__global__ void scan_kernel() {
    __shared__ unsigned long long s0[1024], s1[1024];
    __shared__ int base[NEXP];
    int tid = threadIdx.x;
    if (tid < NEXP) base[tid] = 0;
    __syncthreads();
    for (int chunk = 0; chunk < N_TOK / 1024; chunk++) {
        int n = chunk * 1024 + tid;
        int e = g_idx[n];
        unsigned long long w0 = 0ull, w1 = 0ull;
        if (e < 4) w0 = 1ull << (16 * e);
        else       w1 = 1ull << (16 * (e - 4));
        s0[tid] = w0; s1[tid] = w1;
        __syncthreads();
        for (int off = 1; off < 1024; off <<= 1) {
            unsigned long long a0 = 0ull, a1 = 0ull;
            if (tid >= off) { a0 = s0[tid - off]; a1 = s1[tid - off]; }
            __syncthreads();
            s0[tid] += a0; s1[tid] += a1;
            __syncthreads();
        }
        unsigned long long i0 = s0[tid], i1 = s1[tid];
        unsigned long long t0 = s0[1023], t1 = s1[1023];
        int within = (e < 4) ? (int)((i0 >> (16 * e)) & 0xFFFFull)
                             : (int)((i1 >> (16 * (e - 4))) & 0xFFFFull);
        int pos = base[e] + within;  // 1-based global position within expert
        if (pos < CAP) {
            g_comb[n] = e * CAP + pos;
            g_tok[e * CAP + pos] = n;
        } else {
            g_comb[n] = -1;          // dropped by capacity
        }
        __syncthreads();             // all base reads done
        if (tid < NEXP) {
            int ee = tid;
            base[ee] += (ee < 4) ? (int)((t0 >> (16 * ee)) & 0xFFFFull)
                                 : (int)((t1 >> (16 * (ee - 4))) & 0xFFFFull);
        }
        __syncthreads();
    }
}

// ---------------- dispatch scatter: expert_in[slot] = gate * x[n] -----------
__global__ void dispatch_kernel(const float* __restrict__ x) {
    int slot = blockIdx.x;       // 0..NEXP*CAP-1
    int t = threadIdx.x;         // 256 threads, float4 each -> 1024 floats
    int n = g_tok[slot];
    float4* dst = reinterpret_cast<float4*>(g_expert_in + (size_t)slot * DIM);
    if (n < 0) {
        dst[t] = make_float4(0.f, 0.f, 0.f, 0.f);
    } else {
        float g = g_gate[n];
        float4 v = reinterpret_cast<const float4*>(x + (size_t)n * DIM)[t];
        v.x *= g; v.y *= g; v.z *= g; v.w *= g;
        dst[t] = v;
    }
}

// ---------------- combine gather: out[n] = gate * eo[slot] ------------------
__global__ void combine_kernel(float* __restrict__ out) {
    int n = blockIdx.x;
    int t = threadIdx.x;
    int s = g_comb[n];
    float4* dst = reinterpret_cast<float4*>(out + (size_t)n * DIM);
    if (s < 0) {
        dst[t] = make_float4(0.f, 0.f, 0.f, 0.f);
    } else {
        float g = g_gate[n];
        float4 v = reinterpret_cast<const float4*>(g_eo + (size_t)s * DIM)[t];
        v.x *= g; v.y *= g; v.z *= g; v.w *= g;
        dst[t] = v;
    }
}

// ---------------- packed-f32x2 SGEMM ----------------------------------------
__device__ __forceinline__ unsigned long long splat2(float x) {
    unsigned long long r;
    asm("mov.b64 %0, {%1, %1};" : "=l"(r) : "f"(x));
    return r;
}
__device__ __forceinline__ void ffma2(unsigned long long& d,
                                      unsigned long long a,
                                      unsigned long long b) {
    asm("fma.rn.f32x2 %0, %1, %2, %0;" : "+l"(d) : "l"(a), "l"(b));
}
__device__ __forceinline__ float2 unpack2(unsigned long long v) {
    float2 r;
    asm("mov.b64 {%0, %1}, %2;" : "=f"(r.x), "=f"(r.y) : "l"(v));
    return r;
}

// C[e] = act(A[e] @ B[e] + bias[e]); A,B,C all [1024x1024] row-major per expert.
// 128x128 block tile, BK=16, 256 threads, 8x8 per-thread tile (split 4+4),
// accumulation via fma.rn.f32x2 (2x fp32 FMA throughput on sm_103a).
template <bool RELU>
__global__ void __launch_bounds__(256) sgemm_kernel(
    const float* __restrict__ Ag, const float* __restrict__ Bg,
    const float* __restrict__ biasg, float* __restrict__ Cg) {
    const int ex = blockIdx.z;
    const float* A = Ag + (size_t)ex * DIM * DIM + (size_t)blockIdx.y * 128 * DIM;
    const float* B = Bg + (size_t)ex * DIM * DIM + blockIdx.x * 128;
    const float* bias = biasg + ex * DIM + blockIdx.x * 128;
    float* C = Cg + (size_t)ex * DIM * DIM + (size_t)blockIdx.y * 128 * DIM
                  + blockIdx.x * 128;

    __shared__ float As[16][132];  // [k][m], padded
    __shared__ float Bs[16][128];  // [k][n]

    const int t  = threadIdx.x;
    const int tx = t & 15;
    const int ty = t >> 4;

    const int arow = t >> 2;
    const int acol = (t & 3) << 2;
    const int brow = t >> 5;
    const int bcol = (t & 31) << 2;

    unsigned long long acc[8][4];
#pragma unroll
    for (int i = 0; i < 8; i++)
#pragma unroll
        for (int j = 0; j < 4; j++) acc[i][j] = 0ull;

    for (int k0 = 0; k0 < DIM; k0 += 16) {
#pragma unroll
        for (int i = 0; i < 2; i++) {
            int r = arow + i * 64;
            float4 v = *reinterpret_cast<const float4*>(A + (size_t)r * DIM + k0 + acol);
            As[acol + 0][r] = v.x; As[acol + 1][r] = v.y;
            As[acol + 2][r] = v.z; As[acol + 3][r] = v.w;
        }
#pragma unroll
        for (int i = 0; i < 2; i++) {
            int r = brow + i * 8;
            *reinterpret_cast<float4*>(&Bs[r][bcol]) =
                *reinterpret_cast<const float4*>(B + (size_t)(k0 + r) * DIM + bcol);
        }
        __syncthreads();
#pragma unroll
        for (int k = 0; k < 16; k++) {
            float4 a0 = *reinterpret_cast<const float4*>(&As[k][ty * 4]);
            float4 a1 = *reinterpret_cast<const float4*>(&As[k][ty * 4 + 64]);
            unsigned long long b0 = *reinterpret_cast<const unsigned long long*>(&Bs[k][tx * 4]);
            unsigned long long b1 = *reinterpret_cast<const unsigned long long*>(&Bs[k][tx * 4 + 2]);
            unsigned long long b2 = *reinterpret_cast<const unsigned long long*>(&Bs[k][tx * 4 + 64]);
            unsigned long long b3 = *reinterpret_cast<const unsigned long long*>(&Bs[k][tx * 4 + 66]);
            unsigned long long av[8];
            av[0] = splat2(a0.x); av[1] = splat2(a0.y);
            av[2] = splat2(a0.z); av[3] = splat2(a0.w);
            av[4] = splat2(a1.x); av[5] = splat2(a1.y);
            av[6] = splat2(a1.z); av[7] = splat2(a1.w);
#pragma unroll
            for (int i = 0; i < 8; i++) {
                ffma2(acc[i][0], av[i], b0);
                ffma2(acc[i][1], av[i], b1);
                ffma2(acc[i][2], av[i], b2);
                ffma2(acc[i][3], av[i], b3);
            }
        }
        __syncthreads();
    }

    float4 bias0 = *reinterpret_cast<const float4*>(bias + tx * 4);
    float4 bias1 = *reinterpret_cast<const float4*>(bias + tx * 4 + 64);
#pragma unroll
    for (int i = 0; i < 8; i++) {
        int r = (i < 4) ? (ty * 4 + i) : (ty * 4 + 60 + i);  // +64 for upper half
        float2 p0 = unpack2(acc[i][0]);
        float2 p1 = unpack2(acc[i][1]);
        float2 p2 = unpack2(acc[i][2]);
        float2 p3 = unpack2(acc[i][3]);
        float4 v0 = make_float4(p0.x + bias0.x, p0.y + bias0.y,
                                p1.x + bias0.z, p1.y + bias0.w);
        float4 v1 = make_float4(p2.x + bias1.x, p2.y + bias1.y,
                                p3.x + bias1.z, p3.y + bias1.w);
        if (RELU) {
            v0.x = fmaxf(v0.x, 0.f); v0.y = fmaxf(v0.y, 0.f);
            v0.z = fmaxf(v0.z, 0.f); v0.w = fmaxf(v0.w, 0.f);
            v1.x = fmaxf(v1.x, 0.f); v1.y = fmaxf(v1.y, 0.f);
            v1.z = fmaxf(v1.z, 0.f); v1.w = fmaxf(v1.w, 0.f);
        }
        *reinterpret_cast<float4*>(C + (size_t)r * DIM + tx * 4) = v0;
        *reinterpret_cast<float4*>(C + (size_t)r * DIM + tx * 4 + 64) = v1;
    }
}

// ---------------- launch ------------------------------------------------------
extern "C" void kernel_launch(void* const* d_in, const int* in_sizes, int n_in,
                              void* d_out, int out_size) {
    const float* x  = (const float*)d_in[0];
    const float* Wr = (const float*)d_in[1];
    const float* br = (const float*)d_in[2];
    const float* W1 = (const float*)d_in[3];
    const float* b1 = (const float*)d_in[4];
    const float* W2 = (const float*)d_in[5];
    const float* b2 = (const float*)d_in[6];
    float* out = (float*)d_out;

    void *p_ei = nullptr, *p_h = nullptr, *p_eo = nullptr;
    cudaGetSymbolAddress(&p_ei, g_expert_in);
    cudaGetSymbolAddress(&p_h,  g_h);
    cudaGetSymbolAddress(&p_eo, g_eo);

    router_kernel<<<N_TOK * 32 / 256, 256>>>(x, Wr, br);
    init_tok_kernel<<<(NEXP * CAP + 255) / 256, 256>>>();
    scan_kernel<<<1, 1024>>>();
    dispatch_kernel<<<NEXP * CAP, 256>>>(x);

    dim3 grid(DIM / 128, DIM / 128, NEXP);
    sgemm_kernel<true ><<<grid, 256>>>((const float*)p_ei, W1, b1, (float*)p_h);
    sgemm_kernel<false><<<grid, 256>>>((const float*)p_h,  W2, b2, (float*)p_eo);

    combine_kernel<<<N_TOK, 256>>>(out);
}

// round 3
// speedup vs baseline: 1.8992x; 1.8992x over previous
#include <cuda_runtime.h>
#include <cuda_bf16.h>
#include <cstdint>

#define N_TOK 8192
#define DIM   1024
#define NEXP  8
#define CAP   1024

// ---------------- scratch (device globals; no allocation allowed) ----------
__device__ __nv_bfloat16 g_Ah[(size_t)N_TOK * DIM];   // expert_in hi plane
__device__ __nv_bfloat16 g_Al[(size_t)N_TOK * DIM];   // expert_in lo plane
__device__ __nv_bfloat16 g_Hh[(size_t)N_TOK * DIM];   // hidden hi plane
__device__ __nv_bfloat16 g_Hl[(size_t)N_TOK * DIM];   // hidden lo plane
__device__ __nv_bfloat16 g_B1h[(size_t)N_TOK * DIM];  // W1^T hi  [e][n][k]
__device__ __nv_bfloat16 g_B1l[(size_t)N_TOK * DIM];  // W1^T lo
__device__ __nv_bfloat16 g_B2h[(size_t)N_TOK * DIM];  // W2^T hi
__device__ __nv_bfloat16 g_B2l[(size_t)N_TOK * DIM];  // W2^T lo
__device__ float g_eo[(size_t)N_TOK * DIM];           // expert output fp32
__device__ int   g_idx[N_TOK];
__device__ float g_gate[N_TOK];
__device__ int   g_comb[N_TOK];
__device__ int   g_tok[NEXP * CAP];

// ---------------- PTX helpers (sm_80-level only; no 'a'-gated instrs) -------
__device__ __forceinline__ uint32_t smem_u32(const void* p) {
    uint32_t a;
    asm("{ .reg .u64 t; cvta.to.shared.u64 t, %1; cvt.u32.u64 %0, t; }"
        : "=r"(a) : "l"(p));
    return a;
}

#define CP_ASYNC16(dst, src) \
    asm volatile("cp.async.cg.shared.global [%0], [%1], 16;" :: "r"(dst), "l"(src) : "memory")
#define CP_COMMIT() asm volatile("cp.async.commit_group;" ::: "memory")
#define CP_WAIT2()  asm volatile("cp.async.wait_group 2;" ::: "memory")

#define LDSM_X4(r, addr) \
    asm volatile("ldmatrix.sync.aligned.m8n8.x4.shared.b16 {%0,%1,%2,%3}, [%4];" \
        : "=r"((r)[0]), "=r"((r)[1]), "=r"((r)[2]), "=r"((r)[3]) : "r"(addr))

#define MMA_BF16(d, a, b) \
    asm volatile("mma.sync.aligned.m16n8k16.row.col.f32.bf16.bf16.f32 " \
        "{%0,%1,%2,%3}, {%4,%5,%6,%7}, {%8,%9}, {%0,%1,%2,%3};" \
        : "+f"((d)[0]), "+f"((d)[1]), "+f"((d)[2]), "+f"((d)[3]) \
        : "r"((a)[0]), "r"((a)[1]), "r"((a)[2]), "r"((a)[3]), \
          "r"((b)[0]), "r"((b)[1]))

__device__ __forceinline__ void split_bf16(float v, __nv_bfloat16& h, __nv_bfloat16& l) {
    h = __float2bfloat16(v);
    l = __float2bfloat16(v - __bfloat162float(h));
}
__device__ __forceinline__ uint32_t pk(__nv_bfloat16 a, __nv_bfloat16 b) {
    return (uint32_t)__bfloat16_as_ushort(a) | ((uint32_t)__bfloat16_as_ushort(b) << 16);
}

// ---------------- router: one warp per token --------------------------------
__global__ void router_kernel(const float* __restrict__ x,
                              const float* __restrict__ Wr,
                              const float* __restrict__ br) {
    int gwarp = (blockIdx.x * blockDim.x + threadIdx.x) >> 5;
    int lane  = threadIdx.x & 31;
    if (gwarp >= N_TOK) return;
    const float* xr = x + (size_t)gwarp * DIM;
    float acc[NEXP];
#pragma unroll
    for (int e = 0; e < NEXP; e++) acc[e] = 0.f;
    for (int d = lane; d < DIM; d += 32) {
        float xv = xr[d];
        const float* w = Wr + d * NEXP;
#pragma unroll
        for (int e = 0; e < NEXP; e++) acc[e] += xv * w[e];
    }
#pragma unroll
    for (int o = 16; o > 0; o >>= 1)
#pragma unroll
        for (int e = 0; e < NEXP; e++)
            acc[e] += __shfl_xor_sync(0xffffffffu, acc[e], o);
    if (lane == 0) {
        float m = -1e30f; int ai = 0;
#pragma unroll
        for (int e = 0; e < NEXP; e++) {
            acc[e] += br[e];
            if (acc[e] > m) { m = acc[e]; ai = e; }   // strict > keeps first
        }
        float s = 0.f;
#pragma unroll
        for (int e = 0; e < NEXP; e++) s += expf(acc[e] - m);
        g_idx[gwarp]  = ai;
        g_gate[gwarp] = 1.f / s;
    }
}

__global__ void init_tok_kernel() {
    int i = blockIdx.x * blockDim.x + threadIdx.x;
    if (i < NEXP * CAP) g_tok[i] = -1;
}

// ---------------- order-preserving scan: 8 tokens/thread, 3-level shfl ------
__global__ void scan_kernel() {
    __shared__ unsigned long long w0s[32], w1s[32];
    int tid = threadIdx.x;          // 1024 threads
    int lane = tid & 31;
    int e8[8];
    unsigned long long c0 = 0ull, c1 = 0ull;
#pragma unroll
    for (int i = 0; i < 8; i++) {
        int e = g_idx[tid * 8 + i];
        e8[i] = e;
        if (e < 4) c0 += 1ull << (16 * e);
        else       c1 += 1ull << (16 * (e - 4));
    }
    unsigned long long s0 = c0, s1 = c1;
#pragma unroll
    for (int o = 1; o < 32; o <<= 1) {
        unsigned long long t0 = __shfl_up_sync(0xffffffffu, s0, o);
        unsigned long long t1 = __shfl_up_sync(0xffffffffu, s1, o);
        if (lane >= o) { s0 += t0; s1 += t1; }
    }
    if (lane == 31) { w0s[tid >> 5] = s0; w1s[tid >> 5] = s1; }
    __syncthreads();
    if (tid < 32) {
        unsigned long long a0 = w0s[tid], a1 = w1s[tid];
#pragma unroll
        for (int o = 1; o < 32; o <<= 1) {
            unsigned long long t0 = __shfl_up_sync(0xffffffffu, a0, o);
            unsigned long long t1 = __shfl_up_sync(0xffffffffu, a1, o);
            if (tid >= o) { a0 += t0; a1 += t1; }
        }
        w0s[tid] = a0; w1s[tid] = a1;
    }
    __syncthreads();
    unsigned long long p0 = s0 - c0, p1 = s1 - c1;   // exclusive within warp
    if (tid >= 32) { p0 += w0s[(tid >> 5) - 1]; p1 += w1s[(tid >> 5) - 1]; }
#pragma unroll
    for (int i = 0; i < 8; i++) {
        int n = tid * 8 + i, e = e8[i];
        int pos;
        if (e < 4) { p0 += 1ull << (16 * e);       pos = (int)((p0 >> (16 * e)) & 0xFFFFull); }
        else       { p1 += 1ull << (16 * (e - 4)); pos = (int)((p1 >> (16 * (e - 4))) & 0xFFFFull); }
        if (pos < CAP) {
            g_comb[n] = e * CAP + pos;       // 1-based pos, slot 0 unused
            g_tok[e * CAP + pos] = n;
        } else {
            g_comb[n] = -1;
        }
    }
}

// ---------------- dispatch scatter + hi/lo split -----------------------------
__global__ void dispatch_kernel(const float* __restrict__ x) {
    int slot = blockIdx.x;
    int t = threadIdx.x;  // 256 threads x 4 floats
    int n = g_tok[slot];
    uint2* dh = reinterpret_cast<uint2*>(g_Ah + (size_t)slot * DIM) + t;
    uint2* dl = reinterpret_cast<uint2*>(g_Al + (size_t)slot * DIM) + t;
    if (n < 0) {
        *dh = make_uint2(0u, 0u);
        *dl = make_uint2(0u, 0u);
    } else {
        float g = g_gate[n];
        float4 v = reinterpret_cast<const float4*>(x + (size_t)n * DIM)[t];
        __nv_bfloat16 h0, l0, h1, l1, h2, l2, h3, l3;
        split_bf16(v.x * g, h0, l0);
        split_bf16(v.y * g, h1, l1);
        split_bf16(v.z * g, h2, l2);
        split_bf16(v.w * g, h3, l3);
        *dh = make_uint2(pk(h0, h1), pk(h2, h3));
        *dl = make_uint2(pk(l0, l1), pk(l2, l3));
    }
}

// ---------------- weight transpose + hi/lo split ------------------------------
// in : W[e][k][n] fp32; out: Bt[e][n][k] hi/lo bf16 (K-major for MMA)
__global__ void wt_kernel(const float* __restrict__ W,
                          __nv_bfloat16* __restrict__ Bh,
                          __nv_bfloat16* __restrict__ Bl) {
    __shared__ float ts[32][33];
    int e = blockIdx.z;
    int k0 = blockIdx.y * 32, n0 = blockIdx.x * 32;
    int tx = threadIdx.x, ty = threadIdx.y;  // 32 x 8
    const float* Wb = W + (size_t)e * DIM * DIM;
    for (int i = ty; i < 32; i += 8)
        ts[i][tx] = Wb[(size_t)(k0 + i) * DIM + n0 + tx];
    __syncthreads();
    size_t ob = (size_t)e * DIM * DIM;
    for (int i = ty; i < 32; i += 8) {
        float v = ts[tx][i];
        __nv_bfloat16 h, l;
        split_bf16(v, h, l);
        size_t o = ob + (size_t)(n0 + i) * DIM + k0 + tx;
        Bh[o] = h;
        Bl[o] = l;
    }
}

// ---------------- combine gather ---------------------------------------------
__global__ void combine_kernel(float* __restrict__ out) {
    int n = blockIdx.x;
    int t = threadIdx.x;
    int s = g_comb[n];
    float4* dst = reinterpret_cast<float4*>(out + (size_t)n * DIM);
    if (s < 0) {
        dst[t] = make_float4(0.f, 0.f, 0.f, 0.f);
    } else {
        float g = g_gate[n];
        float4 v = reinterpret_cast<const float4*>(g_eo + (size_t)s * DIM)[t];
        v.x *= g; v.y *= g; v.z *= g; v.w *= g;
        dst[t] = v;
    }
}

// ---------------- split-bf16 GEMM via mma.sync (HMMA) -------------------------
// C[128x128] per CTA. A [8192][1024] hi/lo bf16 K-major; B [8192][1024] hi/lo.
// 3-term: Ah*Bh + Ah*Bl + Al*Bh, fp32 accum in registers.
// smem tile: 128 rows x 128B (BK=64 bf16), SW128-swizzled; 4 planes/stage.
#define STAGES  3
#define TILEB   16384
#define STAGEB  (4 * TILEB)
#define NCHUNK  16
#define GEMM_SMEM (2048 + STAGES * STAGEB)

template <bool SPLIT_RELU>
__global__ void __launch_bounds__(256, 1) gemm_mma(
    const __nv_bfloat16* __restrict__ Ah, const __nv_bfloat16* __restrict__ Al,
    const __nv_bfloat16* __restrict__ Bh, const __nv_bfloat16* __restrict__ Bl,
    const float* __restrict__ bias,
    __nv_bfloat16* __restrict__ outH, __nv_bfloat16* __restrict__ outL,
    float* __restrict__ outF) {
    extern __shared__ char smem[];
    uint32_t raw = smem_u32(smem);
    uint32_t tiles = (raw + 512 + 1023) & ~1023u;
    float* sb = reinterpret_cast<float*>(smem + (tiles - 512 - raw)); // 128 floats

    const int tid = threadIdx.x;
    const int lane = tid & 31, wid = tid >> 5;
    const int bx = blockIdx.x, by = blockIdx.y, ex = blockIdx.z;

    const size_t rowA0 = (size_t)ex * 1024 + (size_t)by * 128;
    const size_t rowB0 = (size_t)ex * 1024 + (size_t)bx * 128;
    const char* pA[4] = {
        (const char*)(Ah + rowA0 * DIM), (const char*)(Al + rowA0 * DIM),
        (const char*)(Bh + rowB0 * DIM), (const char*)(Bl + rowB0 * DIM)};

    if (tid < 128) sb[tid] = bias[ex * DIM + bx * 128 + tid];

    auto load_chunk = [&](int c, int s) {
        uint32_t st = tiles + s * STAGEB;
        int kb = c * 128;  // byte offset within a K-row (64 bf16 = 128B)
#pragma unroll
        for (int i = 0; i < 16; i++) {
            int g = tid + i * 256;        // 0..4095
            int tile = g >> 10;
            int j = g & 1023;
            int row = j >> 3, seg = j & 7;
            uint32_t dst = st + tile * TILEB + row * 128 + ((seg ^ (row & 7)) << 4);
            const char* src = pA[tile] + (size_t)row * (DIM * 2) + kb + seg * 16;
            CP_ASYNC16(dst, src);
        }
    };

    load_chunk(0, 0); CP_COMMIT();
    load_chunk(1, 1); CP_COMMIT();
    load_chunk(2, 2); CP_COMMIT();

    float acc[4][4][4];
#pragma unroll
    for (int i = 0; i < 4; i++)
#pragma unroll
        for (int j = 0; j < 4; j++)
#pragma unroll
            for (int q = 0; q < 4; q++) acc[i][j][q] = 0.f;

    const int m_off = (wid & 1) * 64;    // warp tile 64x32; warps 2x4
    const int n_off = (wid >> 1) * 32;
    const int grp = lane >> 3, loc = lane & 7;
    const int rowoff_a = (grp & 1) * 8 + loc;   // A: M0(r0-7,k0) M1(r8-15,k0) M2(r0-7,k8) M3(r8-15,k8)
    const int segoff_a = grp >> 1;
    const int rowoff_b = (grp >> 1) * 8 + loc;  // B: M0(n0-7,k0) M1(n0-7,k8) M2(n8-15,k0) M3(n8-15,k8)
    const int segoff_b = grp & 1;

    for (int c = 0; c < NCHUNK; c++) {
        int s = c % STAGES;
        CP_WAIT2();
        __syncthreads();
        uint32_t st = tiles + s * STAGEB;
#pragma unroll
        for (int ks = 0; ks < 4; ks++) {
            int seg0 = ks * 2;
            uint32_t aH[4][4], aL[4][4], bH[4][2], bL[4][2];
#pragma unroll
            for (int mt = 0; mt < 4; mt++) {
                int row = m_off + mt * 16 + rowoff_a;
                int seg = seg0 + segoff_a;
                uint32_t ad = st + row * 128 + ((seg ^ (row & 7)) << 4);
                LDSM_X4(aH[mt], ad);
                LDSM_X4(aL[mt], ad + TILEB);
            }
#pragma unroll
            for (int p = 0; p < 2; p++) {
                int row = n_off + p * 16 + rowoff_b;
                int seg = seg0 + segoff_b;
                uint32_t bd = st + 2 * TILEB + row * 128 + ((seg ^ (row & 7)) << 4);
                uint32_t r[4];
                LDSM_X4(r, bd);
                bH[2 * p][0] = r[0]; bH[2 * p][1] = r[1];
                bH[2 * p + 1][0] = r[2]; bH[2 * p + 1][1] = r[3];
                LDSM_X4(r, bd + TILEB);
                bL[2 * p][0] = r[0]; bL[2 * p][1] = r[1];
                bL[2 * p + 1][0] = r[2]; bL[2 * p + 1][1] = r[3];
            }
#pragma unroll
            for (int mt = 0; mt < 4; mt++)
#pragma unroll
                for (int nt = 0; nt < 4; nt++) {
                    MMA_BF16(acc[mt][nt], aH[mt], bH[nt]);
                    MMA_BF16(acc[mt][nt], aH[mt], bL[nt]);
                    MMA_BF16(acc[mt][nt], aL[mt], bH[nt]);
                }
        }
        __syncthreads();
        if (c + STAGES < NCHUNK) load_chunk(c + STAGES, s);
        CP_COMMIT();
    }

    // ---- epilogue ----
    const int colb = bx * 128;
#pragma unroll
    for (int mt = 0; mt < 4; mt++) {
        size_t gr0 = rowA0 + m_off + mt * 16 + (lane >> 2);
        size_t gr1 = gr0 + 8;
#pragma unroll
        for (int nt = 0; nt < 4; nt++) {
            int cl = n_off + nt * 8 + 2 * (lane & 3);
            float b0 = sb[cl], b1 = sb[cl + 1];
            float v00 = acc[mt][nt][0] + b0, v01 = acc[mt][nt][1] + b1;
            float v10 = acc[mt][nt][2] + b0, v11 = acc[mt][nt][3] + b1;
            if (SPLIT_RELU) {
                v00 = fmaxf(v00, 0.f); v01 = fmaxf(v01, 0.f);
                v10 = fmaxf(v10, 0.f); v11 = fmaxf(v11, 0.f);
                __nv_bfloat16 h0, l0, h1, l1;
                split_bf16(v00, h0, l0); split_bf16(v01, h1, l1);
                *reinterpret_cast<uint32_t*>(outH + gr0 * DIM + colb + cl) = pk(h0, h1);
                *reinterpret_cast<uint32_t*>(outL + gr0 * DIM + colb + cl) = pk(l0, l1);
                split_bf16(v10, h0, l0); split_bf16(v11, h1, l1);
                *reinterpret_cast<uint32_t*>(outH + gr1 * DIM + colb + cl) = pk(h0, h1);
                *reinterpret_cast<uint32_t*>(outL + gr1 * DIM + colb + cl) = pk(l0, l1);
            } else {
                *reinterpret_cast<float2*>(outF + gr0 * DIM + colb + cl) = make_float2(v00, v01);
                *reinterpret_cast<float2*>(outF + gr1 * DIM + colb + cl) = make_float2(v10, v11);
            }
        }
    }
}

// ---------------- launch -------------------------------------------------------
extern "C" void kernel_launch(void* const* d_in, const int* in_sizes, int n_in,
                              void* d_out, int out_size) {
    const float* x  = (const float*)d_in[0];
    const float* Wr = (const float*)d_in[1];
    const float* br = (const float*)d_in[2];
    const float* W1 = (const float*)d_in[3];
    const float* b1 = (const float*)d_in[4];
    const float* W2 = (const float*)d_in[5];
    const float* b2 = (const float*)d_in[6];
    float* out = (float*)d_out;

    void *pAh, *pAl, *pHh, *pHl, *pB1h, *pB1l, *pB2h, *pB2l, *pEo;
    cudaGetSymbolAddress(&pAh, g_Ah);   cudaGetSymbolAddress(&pAl, g_Al);
    cudaGetSymbolAddress(&pHh, g_Hh);   cudaGetSymbolAddress(&pHl, g_Hl);
    cudaGetSymbolAddress(&pB1h, g_B1h); cudaGetSymbolAddress(&pB1l, g_B1l);
    cudaGetSymbolAddress(&pB2h, g_B2h); cudaGetSymbolAddress(&pB2l, g_B2l);
    cudaGetSymbolAddress(&pEo, g_eo);

    cudaFuncSetAttribute(gemm_mma<true>,  cudaFuncAttributeMaxDynamicSharedMemorySize, GEMM_SMEM);
    cudaFuncSetAttribute(gemm_mma<false>, cudaFuncAttributeMaxDynamicSharedMemorySize, GEMM_SMEM);

    router_kernel<<<N_TOK * 32 / 256, 256>>>(x, Wr, br);
    init_tok_kernel<<<(NEXP * CAP + 255) / 256, 256>>>();
    scan_kernel<<<1, 1024>>>();
    dispatch_kernel<<<NEXP * CAP, 256>>>(x);

    dim3 wtg(32, 32, NEXP);
    wt_kernel<<<wtg, dim3(32, 8)>>>(W1, (__nv_bfloat16*)pB1h, (__nv_bfloat16*)pB1l);
    wt_kernel<<<wtg, dim3(32, 8)>>>(W2, (__nv_bfloat16*)pB2h, (__nv_bfloat16*)pB2l);

    dim3 gg(8, 8, NEXP);
    gemm_mma<true><<<gg, 256, GEMM_SMEM>>>(
        (const __nv_bfloat16*)pAh, (const __nv_bfloat16*)pAl,
        (const __nv_bfloat16*)pB1h, (const __nv_bfloat16*)pB1l,
        b1, (__nv_bfloat16*)pHh, (__nv_bfloat16*)pHl, nullptr);
    gemm_mma<false><<<gg, 256, GEMM_SMEM>>>(
        (const __nv_bfloat16*)pHh, (const __nv_bfloat16*)pHl,
        (const __nv_bfloat16*)pB2h, (const __nv_bfloat16*)pB2l,
        b2, nullptr, nullptr, (float*)pEo);

    combine_kernel<<<N_TOK, 256>>>(out);
}

// round 4
// speedup vs baseline: 1.9391x; 1.0210x over previous
#include <cuda_runtime.h>
#include <cuda_bf16.h>
#include <cstdint>

#define N_TOK 8192
#define DIM   1024
#define NEXP  8
#define CAP   1024

// ---------------- scratch (device globals; no allocation allowed) ----------
__device__ __nv_bfloat16 g_Ah[(size_t)N_TOK * DIM];   // expert_in hi plane
__device__ __nv_bfloat16 g_Al[(size_t)N_TOK * DIM];   // expert_in lo plane
__device__ __nv_bfloat16 g_Hh[(size_t)N_TOK * DIM];   // hidden hi plane
__device__ __nv_bfloat16 g_Hl[(size_t)N_TOK * DIM];   // hidden lo plane
__device__ __nv_bfloat16 g_B1h[(size_t)N_TOK * DIM];  // W1^T hi  [e][n][k]
__device__ __nv_bfloat16 g_B1l[(size_t)N_TOK * DIM];  // W1^T lo
__device__ __nv_bfloat16 g_B2h[(size_t)N_TOK * DIM];  // W2^T hi
__device__ __nv_bfloat16 g_B2l[(size_t)N_TOK * DIM];  // W2^T lo
__device__ int   g_idx[N_TOK];
__device__ float g_gate[N_TOK];
__device__ int   g_comb[N_TOK];
__device__ int   g_tok[NEXP * CAP];

// ---------------- PTX helpers (sm_80-level only) -----------------------------
__device__ __forceinline__ uint32_t smem_u32(const void* p) {
    uint32_t a;
    asm("{ .reg .u64 t; cvta.to.shared.u64 t, %1; cvt.u32.u64 %0, t; }"
        : "=r"(a) : "l"(p));
    return a;
}

#define CP_ASYNC16(dst, src) \
    asm volatile("cp.async.cg.shared.global [%0], [%1], 16;" :: "r"(dst), "l"(src) : "memory")
#define CP_COMMIT() asm volatile("cp.async.commit_group;" ::: "memory")
#define CP_WAIT1()  asm volatile("cp.async.wait_group 1;" ::: "memory")

#define LDSM_X4(r, addr) \
    asm volatile("ldmatrix.sync.aligned.m8n8.x4.shared.b16 {%0,%1,%2,%3}, [%4];" \
        : "=r"((r)[0]), "=r"((r)[1]), "=r"((r)[2]), "=r"((r)[3]) : "r"(addr))

#define MMA_BF16(d, a, b) \
    asm volatile("mma.sync.aligned.m16n8k16.row.col.f32.bf16.bf16.f32 " \
        "{%0,%1,%2,%3}, {%4,%5,%6,%7}, {%8,%9}, {%0,%1,%2,%3};" \
        : "+f"((d)[0]), "+f"((d)[1]), "+f"((d)[2]), "+f"((d)[3]) \
        : "r"((a)[0]), "r"((a)[1]), "r"((a)[2]), "r"((a)[3]), \
          "r"((b)[0]), "r"((b)[1]))

__device__ __forceinline__ void split_bf16(float v, __nv_bfloat16& h, __nv_bfloat16& l) {
    h = __float2bfloat16(v);
    l = __float2bfloat16(v - __bfloat162float(h));
}
__device__ __forceinline__ uint32_t pk(__nv_bfloat16 a, __nv_bfloat16 b) {
    return (uint32_t)__bfloat16_as_ushort(a) | ((uint32_t)__bfloat16_as_ushort(b) << 16);
}

// ---------------- router (+ g_tok init fused): one warp per token -----------
__global__ void router_kernel(const float* __restrict__ x,
                              const float* __restrict__ Wr,
                              const float* __restrict__ br) {
    int gid = blockIdx.x * blockDim.x + threadIdx.x;
    if (gid < NEXP * CAP) g_tok[gid] = -1;
    int gwarp = gid >> 5;
    int lane  = threadIdx.x & 31;
    if (gwarp >= N_TOK) return;
    const float* xr = x + (size_t)gwarp * DIM;
    float acc[NEXP];
#pragma unroll
    for (int e = 0; e < NEXP; e++) acc[e] = 0.f;
    for (int d = lane; d < DIM; d += 32) {
        float xv = xr[d];
        const float* w = Wr + d * NEXP;
#pragma unroll
        for (int e = 0; e < NEXP; e++) acc[e] += xv * w[e];
    }
#pragma unroll
    for (int o = 16; o > 0; o >>= 1)
#pragma unroll
        for (int e = 0; e < NEXP; e++)
            acc[e] += __shfl_xor_sync(0xffffffffu, acc[e], o);
    if (lane == 0) {
        float m = -1e30f; int ai = 0;
#pragma unroll
        for (int e = 0; e < NEXP; e++) {
            acc[e] += br[e];
            if (acc[e] > m) { m = acc[e]; ai = e; }   // strict > keeps first
        }
        float s = 0.f;
#pragma unroll
        for (int e = 0; e < NEXP; e++) s += expf(acc[e] - m);
        g_idx[gwarp]  = ai;
        g_gate[gwarp] = 1.f / s;
    }
}

// ---------------- order-preserving scan: 8 tokens/thread, 3-level shfl ------
__global__ void scan_kernel() {
    __shared__ unsigned long long w0s[32], w1s[32];
    int tid = threadIdx.x;          // 1024 threads
    int lane = tid & 31;
    int e8[8];
    unsigned long long c0 = 0ull, c1 = 0ull;
#pragma unroll
    for (int i = 0; i < 8; i++) {
        int e = g_idx[tid * 8 + i];
        e8[i] = e;
        if (e < 4) c0 += 1ull << (16 * e);
        else       c1 += 1ull << (16 * (e - 4));
    }
    unsigned long long s0 = c0, s1 = c1;
#pragma unroll
    for (int o = 1; o < 32; o <<= 1) {
        unsigned long long t0 = __shfl_up_sync(0xffffffffu, s0, o);
        unsigned long long t1 = __shfl_up_sync(0xffffffffu, s1, o);
        if (lane >= o) { s0 += t0; s1 += t1; }
    }
    if (lane == 31) { w0s[tid >> 5] = s0; w1s[tid >> 5] = s1; }
    __syncthreads();
    if (tid < 32) {
        unsigned long long a0 = w0s[tid], a1 = w1s[tid];
#pragma unroll
        for (int o = 1; o < 32; o <<= 1) {
            unsigned long long t0 = __shfl_up_sync(0xffffffffu, a0, o);
            unsigned long long t1 = __shfl_up_sync(0xffffffffu, a1, o);
            if (tid >= o) { a0 += t0; a1 += t1; }
        }
        w0s[tid] = a0; w1s[tid] = a1;
    }
    __syncthreads();
    unsigned long long p0 = s0 - c0, p1 = s1 - c1;   // exclusive within warp
    if (tid >= 32) { p0 += w0s[(tid >> 5) - 1]; p1 += w1s[(tid >> 5) - 1]; }
#pragma unroll
    for (int i = 0; i < 8; i++) {
        int n = tid * 8 + i, e = e8[i];
        int pos;
        if (e < 4) { p0 += 1ull << (16 * e);       pos = (int)((p0 >> (16 * e)) & 0xFFFFull); }
        else       { p1 += 1ull << (16 * (e - 4)); pos = (int)((p1 >> (16 * (e - 4))) & 0xFFFFull); }
        if (pos < CAP) {
            g_comb[n] = e * CAP + pos;       // 1-based pos, slot 0 unused
            g_tok[e * CAP + pos] = n;
        } else {
            g_comb[n] = -1;
        }
    }
}

// ---------------- dispatch scatter + hi/lo split -----------------------------
__global__ void dispatch_kernel(const float* __restrict__ x) {
    int slot = blockIdx.x;
    int t = threadIdx.x;  // 256 threads x 4 floats
    int n = g_tok[slot];
    uint2* dh = reinterpret_cast<uint2*>(g_Ah + (size_t)slot * DIM) + t;
    uint2* dl = reinterpret_cast<uint2*>(g_Al + (size_t)slot * DIM) + t;
    if (n < 0) {
        *dh = make_uint2(0u, 0u);
        *dl = make_uint2(0u, 0u);
    } else {
        float g = g_gate[n];
        float4 v = reinterpret_cast<const float4*>(x + (size_t)n * DIM)[t];
        __nv_bfloat16 h0, l0, h1, l1, h2, l2, h3, l3;
        split_bf16(v.x * g, h0, l0);
        split_bf16(v.y * g, h1, l1);
        split_bf16(v.z * g, h2, l2);
        split_bf16(v.w * g, h3, l3);
        *dh = make_uint2(pk(h0, h1), pk(h2, h3));
        *dl = make_uint2(pk(l0, l1), pk(l2, l3));
    }
}

// ---------------- weight transpose + hi/lo split ------------------------------
__global__ void wt_kernel(const float* __restrict__ W,
                          __nv_bfloat16* __restrict__ Bh,
                          __nv_bfloat16* __restrict__ Bl) {
    __shared__ float ts[32][33];
    int e = blockIdx.z;
    int k0 = blockIdx.y * 32, n0 = blockIdx.x * 32;
    int tx = threadIdx.x, ty = threadIdx.y;  // 32 x 8
    const float* Wb = W + (size_t)e * DIM * DIM;
    for (int i = ty; i < 32; i += 8)
        ts[i][tx] = Wb[(size_t)(k0 + i) * DIM + n0 + tx];
    __syncthreads();
    size_t ob = (size_t)e * DIM * DIM;
    for (int i = ty; i < 32; i += 8) {
        float v = ts[tx][i];
        __nv_bfloat16 h, l;
        split_bf16(v, h, l);
        size_t o = ob + (size_t)(n0 + i) * DIM + k0 + tx;
        Bh[o] = h;
        Bl[o] = l;
    }
}

// ---------------- zero rows of dropped tokens --------------------------------
__global__ void dropzero_kernel(float* __restrict__ out) {
    int n = blockIdx.x;
    if (g_comb[n] >= 0) return;
    reinterpret_cast<float4*>(out + (size_t)n * DIM)[threadIdx.x] =
        make_float4(0.f, 0.f, 0.f, 0.f);
}

// ---------------- split-bf16 GEMM via mma.sync (HMMA) -------------------------
// C[128x128] per CTA. 3-term: Ah*Bh + Ah*Bl + Al*Bh, fp32 accum in registers.
// Pipeline: wait_group(1) -> barrier -> issue loads(c+2) -> MMA(c).
#define STAGES  3
#define TILEB   16384
#define STAGEB  (4 * TILEB)
#define NCHUNK  16
#define GEMM_SMEM (2048 + STAGES * STAGEB)

template <bool SPLIT_RELU>
__global__ void __launch_bounds__(256, 1) gemm_mma(
    const __nv_bfloat16* __restrict__ Ah, const __nv_bfloat16* __restrict__ Al,
    const __nv_bfloat16* __restrict__ Bh, const __nv_bfloat16* __restrict__ Bl,
    const float* __restrict__ bias,
    __nv_bfloat16* __restrict__ outH, __nv_bfloat16* __restrict__ outL,
    float* __restrict__ outF) {
    extern __shared__ char smem[];
    uint32_t raw = smem_u32(smem);
    uint32_t tiles = (raw + 512 + 1023) & ~1023u;
    float* sb = reinterpret_cast<float*>(smem + (tiles - 512 - raw)); // 128 floats

    const int tid = threadIdx.x;
    const int lane = tid & 31, wid = tid >> 5;
    const int bx = blockIdx.x, by = blockIdx.y, ex = blockIdx.z;

    const size_t rowA0 = (size_t)ex * 1024 + (size_t)by * 128;
    const size_t rowB0 = (size_t)ex * 1024 + (size_t)bx * 128;
    const char* pA[4] = {
        (const char*)(Ah + rowA0 * DIM), (const char*)(Al + rowA0 * DIM),
        (const char*)(Bh + rowB0 * DIM), (const char*)(Bl + rowB0 * DIM)};

    if (tid < 128) sb[tid] = bias[ex * DIM + bx * 128 + tid];

    auto load_chunk = [&](int c, int s) {
        uint32_t st = tiles + s * STAGEB;
        int kb = c * 128;  // byte offset within a K-row (64 bf16 = 128B)
#pragma unroll
        for (int i = 0; i < 16; i++) {
            int g = tid + i * 256;        // 0..4095
            int tile = g >> 10;
            int j = g & 1023;
            int row = j >> 3, seg = j & 7;
            uint32_t dst = st + tile * TILEB + row * 128 + ((seg ^ (row & 7)) << 4);
            const char* src = pA[tile] + (size_t)row * (DIM * 2) + kb + seg * 16;
            CP_ASYNC16(dst, src);
        }
    };

    load_chunk(0, 0); CP_COMMIT();
    load_chunk(1, 1); CP_COMMIT();

    float acc[4][4][4];
#pragma unroll
    for (int i = 0; i < 4; i++)
#pragma unroll
        for (int j = 0; j < 4; j++)
#pragma unroll
            for (int q = 0; q < 4; q++) acc[i][j][q] = 0.f;

    const int m_off = (wid & 1) * 64;    // warp tile 64x32; warps 2x4
    const int n_off = (wid >> 1) * 32;
    const int grp = lane >> 3, loc = lane & 7;
    const int rowoff_a = (grp & 1) * 8 + loc;
    const int segoff_a = grp >> 1;
    const int rowoff_b = (grp >> 1) * 8 + loc;
    const int segoff_b = grp & 1;

    for (int c = 0; c < NCHUNK; c++) {
        int s = c % STAGES;
        CP_WAIT1();                 // chunk c resident (c+1 still in flight)
        __syncthreads();            // WAR: all warps done reading stage (c+2)%3
        if (c + 2 < NCHUNK) load_chunk(c + 2, (c + 2) % STAGES);
        CP_COMMIT();                // commit (possibly empty) keeps group count aligned
        uint32_t st = tiles + s * STAGEB;
#pragma unroll
        for (int ks = 0; ks < 4; ks++) {
            int seg0 = ks * 2;
            uint32_t aH[4][4], aL[4][4], bH[4][2], bL[4][2];
#pragma unroll
            for (int mt = 0; mt < 4; mt++) {
                int row = m_off + mt * 16 + rowoff_a;
                int seg = seg0 + segoff_a;
                uint32_t ad = st + row * 128 + ((seg ^ (row & 7)) << 4);
                LDSM_X4(aH[mt], ad);
                LDSM_X4(aL[mt], ad + TILEB);
            }
#pragma unroll
            for (int p = 0; p < 2; p++) {
                int row = n_off + p * 16 + rowoff_b;
                int seg = seg0 + segoff_b;
                uint32_t bd = st + 2 * TILEB + row * 128 + ((seg ^ (row & 7)) << 4);
                uint32_t r[4];
                LDSM_X4(r, bd);
                bH[2 * p][0] = r[0]; bH[2 * p][1] = r[1];
                bH[2 * p + 1][0] = r[2]; bH[2 * p + 1][1] = r[3];
                LDSM_X4(r, bd + TILEB);
                bL[2 * p][0] = r[0]; bL[2 * p][1] = r[1];
                bL[2 * p + 1][0] = r[2]; bL[2 * p + 1][1] = r[3];
            }
#pragma unroll
            for (int mt = 0; mt < 4; mt++)
#pragma unroll
                for (int nt = 0; nt < 4; nt++) {
                    MMA_BF16(acc[mt][nt], aH[mt], bH[nt]);
                    MMA_BF16(acc[mt][nt], aH[mt], bL[nt]);
                    MMA_BF16(acc[mt][nt], aL[mt], bH[nt]);
                }
        }
    }

    // ---- epilogue ----
    const int colb = bx * 128;
#pragma unroll
    for (int mt = 0; mt < 4; mt++) {
        size_t slot0 = rowA0 + m_off + mt * 16 + (lane >> 2);
        size_t slot1 = slot0 + 8;
        int tok0 = 0, tok1 = 0;
        float gt0 = 0.f, gt1 = 0.f;
        if (!SPLIT_RELU) {
            tok0 = g_tok[slot0];
            tok1 = g_tok[slot1];
            gt0 = (tok0 >= 0) ? g_gate[tok0] : 0.f;
            gt1 = (tok1 >= 0) ? g_gate[tok1] : 0.f;
        }
#pragma unroll
        for (int nt = 0; nt < 4; nt++) {
            int cl = n_off + nt * 8 + 2 * (lane & 3);
            float b0 = sb[cl], b1 = sb[cl + 1];
            float v00 = acc[mt][nt][0] + b0, v01 = acc[mt][nt][1] + b1;
            float v10 = acc[mt][nt][2] + b0, v11 = acc[mt][nt][3] + b1;
            if (SPLIT_RELU) {
                v00 = fmaxf(v00, 0.f); v01 = fmaxf(v01, 0.f);
                v10 = fmaxf(v10, 0.f); v11 = fmaxf(v11, 0.f);
                __nv_bfloat16 h0, l0, h1, l1;
                split_bf16(v00, h0, l0); split_bf16(v01, h1, l1);
                *reinterpret_cast<uint32_t*>(outH + slot0 * DIM + colb + cl) = pk(h0, h1);
                *reinterpret_cast<uint32_t*>(outL + slot0 * DIM + colb + cl) = pk(l0, l1);
                split_bf16(v10, h0, l0); split_bf16(v11, h1, l1);
                *reinterpret_cast<uint32_t*>(outH + slot1 * DIM + colb + cl) = pk(h0, h1);
                *reinterpret_cast<uint32_t*>(outL + slot1 * DIM + colb + cl) = pk(l0, l1);
            } else {
                // fused combine: out[token] = gate * (eo + bias)
                if (tok0 >= 0)
                    *reinterpret_cast<float2*>(outF + (size_t)tok0 * DIM + colb + cl) =
                        make_float2(gt0 * v00, gt0 * v01);
                if (tok1 >= 0)
                    *reinterpret_cast<float2*>(outF + (size_t)tok1 * DIM + colb + cl) =
                        make_float2(gt1 * v10, gt1 * v11);
            }
        }
    }
}

// ---------------- launch -------------------------------------------------------
extern "C" void kernel_launch(void* const* d_in, const int* in_sizes, int n_in,
                              void* d_out, int out_size) {
    const float* x  = (const float*)d_in[0];
    const float* Wr = (const float*)d_in[1];
    const float* br = (const float*)d_in[2];
    const float* W1 = (const float*)d_in[3];
    const float* b1 = (const float*)d_in[4];
    const float* W2 = (const float*)d_in[5];
    const float* b2 = (const float*)d_in[6];
    float* out = (float*)d_out;

    void *pAh, *pAl, *pHh, *pHl, *pB1h, *pB1l, *pB2h, *pB2l;
    cudaGetSymbolAddress(&pAh, g_Ah);   cudaGetSymbolAddress(&pAl, g_Al);
    cudaGetSymbolAddress(&pHh, g_Hh);   cudaGetSymbolAddress(&pHl, g_Hl);
    cudaGetSymbolAddress(&pB1h, g_B1h); cudaGetSymbolAddress(&pB1l, g_B1l);
    cudaGetSymbolAddress(&pB2h, g_B2h); cudaGetSymbolAddress(&pB2l, g_B2l);

    cudaFuncSetAttribute(gemm_mma<true>,  cudaFuncAttributeMaxDynamicSharedMemorySize, GEMM_SMEM);
    cudaFuncSetAttribute(gemm_mma<false>, cudaFuncAttributeMaxDynamicSharedMemorySize, GEMM_SMEM);

    router_kernel<<<N_TOK * 32 / 256, 256>>>(x, Wr, br);
    scan_kernel<<<1, 1024>>>();
    dispatch_kernel<<<NEXP * CAP, 256>>>(x);

    dim3 wtg(32, 32, NEXP);
    wt_kernel<<<wtg, dim3(32, 8)>>>(W1, (__nv_bfloat16*)pB1h, (__nv_bfloat16*)pB1l);
    wt_kernel<<<wtg, dim3(32, 8)>>>(W2, (__nv_bfloat16*)pB2h, (__nv_bfloat16*)pB2l);
    dropzero_kernel<<<N_TOK, 256>>>(out);

    dim3 gg(8, 8, NEXP);
    gemm_mma<true><<<gg, 256, GEMM_SMEM>>>(
        (const __nv_bfloat16*)pAh, (const __nv_bfloat16*)pAl,
        (const __nv_bfloat16*)pB1h, (const __nv_bfloat16*)pB1l,
        b1, (__nv_bfloat16*)pHh, (__nv_bfloat16*)pHl, nullptr);
    gemm_mma<false><<<gg, 256, GEMM_SMEM>>>(
        (const __nv_bfloat16*)pHh, (const __nv_bfloat16*)pHl,
        (const __nv_bfloat16*)pB2h, (const __nv_bfloat16*)pB2l,
        b2, nullptr, nullptr, out);
}

// round 5
// speedup vs baseline: 1.9649x; 1.0133x over previous
#include <cuda_runtime.h>
#include <cuda_bf16.h>
#include <cstdint>

#define N_TOK 8192
#define DIM   1024
#define NEXP  8
#define CAP   1024

// ---------------- scratch (device globals; no allocation allowed) ----------
__device__ __nv_bfloat16 g_Ah[(size_t)N_TOK * DIM];   // expert_in hi plane
__device__ __nv_bfloat16 g_Al[(size_t)N_TOK * DIM];   // expert_in lo plane
__device__ __nv_bfloat16 g_Hh[(size_t)N_TOK * DIM];   // hidden hi plane
__device__ __nv_bfloat16 g_Hl[(size_t)N_TOK * DIM];   // hidden lo plane
__device__ __nv_bfloat16 g_B1h[(size_t)N_TOK * DIM];  // W1^T hi  [e][n][k]
__device__ __nv_bfloat16 g_B1l[(size_t)N_TOK * DIM];  // W1^T lo
__device__ __nv_bfloat16 g_B2h[(size_t)N_TOK * DIM];  // W2^T hi
__device__ __nv_bfloat16 g_B2l[(size_t)N_TOK * DIM];  // W2^T lo
__device__ int   g_idx[N_TOK];
__device__ float g_gate[N_TOK];
__device__ int   g_comb[N_TOK];
__device__ int   g_tok[NEXP * CAP];

// ---------------- PTX helpers (sm_80-level only) -----------------------------
__device__ __forceinline__ uint32_t smem_u32(const void* p) {
    uint32_t a;
    asm("{ .reg .u64 t; cvta.to.shared.u64 t, %1; cvt.u32.u64 %0, t; }"
        : "=r"(a) : "l"(p));
    return a;
}

#define CP_ASYNC16(dst, src) \
    asm volatile("cp.async.cg.shared.global [%0], [%1], 16;" :: "r"(dst), "l"(src) : "memory")
#define CP_COMMIT() asm volatile("cp.async.commit_group;" ::: "memory")
#define CP_WAIT1()  asm volatile("cp.async.wait_group 1;" ::: "memory")

#define LDSM_X4(r, addr) \
    asm volatile("ldmatrix.sync.aligned.m8n8.x4.shared.b16 {%0,%1,%2,%3}, [%4];" \
        : "=r"((r)[0]), "=r"((r)[1]), "=r"((r)[2]), "=r"((r)[3]) : "r"(addr))

#define MMA_BF16(d, a, b) \
    asm volatile("mma.sync.aligned.m16n8k16.row.col.f32.bf16.bf16.f32 " \
        "{%0,%1,%2,%3}, {%4,%5,%6,%7}, {%8,%9}, {%0,%1,%2,%3};" \
        : "+f"((d)[0]), "+f"((d)[1]), "+f"((d)[2]), "+f"((d)[3]) \
        : "r"((a)[0]), "r"((a)[1]), "r"((a)[2]), "r"((a)[3]), \
          "r"((b)[0]), "r"((b)[1]))

__device__ __forceinline__ void split_bf16(float v, __nv_bfloat16& h, __nv_bfloat16& l) {
    h = __float2bfloat16(v);
    l = __float2bfloat16(v - __bfloat162float(h));
}
__device__ __forceinline__ uint32_t pk(__nv_bfloat16 a, __nv_bfloat16 b) {
    return (uint32_t)__bfloat16_as_ushort(a) | ((uint32_t)__bfloat16_as_ushort(b) << 16);
}

// ---------------- router (+ g_tok init fused): one warp per token -----------
__global__ void router_kernel(const float* __restrict__ x,
                              const float* __restrict__ Wr,
                              const float* __restrict__ br) {
    int gid = blockIdx.x * blockDim.x + threadIdx.x;
    if (gid < NEXP * CAP) g_tok[gid] = -1;
    int gwarp = gid >> 5;
    int lane  = threadIdx.x & 31;
    if (gwarp >= N_TOK) return;
    const float* xr = x + (size_t)gwarp * DIM;
    float acc[NEXP];
#pragma unroll
    for (int e = 0; e < NEXP; e++) acc[e] = 0.f;
    for (int d = lane; d < DIM; d += 32) {
        float xv = xr[d];
        const float* w = Wr + d * NEXP;
#pragma unroll
        for (int e = 0; e < NEXP; e++) acc[e] += xv * w[e];
    }
#pragma unroll
    for (int o = 16; o > 0; o >>= 1)
#pragma unroll
        for (int e = 0; e < NEXP; e++)
            acc[e] += __shfl_xor_sync(0xffffffffu, acc[e], o);
    if (lane == 0) {
        float m = -1e30f; int ai = 0;
#pragma unroll
        for (int e = 0; e < NEXP; e++) {
            acc[e] += br[e];
            if (acc[e] > m) { m = acc[e]; ai = e; }   // strict > keeps first
        }
        float s = 0.f;
#pragma unroll
        for (int e = 0; e < NEXP; e++) s += expf(acc[e] - m);
        g_idx[gwarp]  = ai;
        g_gate[gwarp] = 1.f / s;
    }
}

// ---------------- order-preserving scan: 8 tokens/thread, 3-level shfl ------
__global__ void scan_kernel() {
    __shared__ unsigned long long w0s[32], w1s[32];
    int tid = threadIdx.x;          // 1024 threads
    int lane = tid & 31;
    int e8[8];
    unsigned long long c0 = 0ull, c1 = 0ull;
#pragma unroll
    for (int i = 0; i < 8; i++) {
        int e = g_idx[tid * 8 + i];
        e8[i] = e;
        if (e < 4) c0 += 1ull << (16 * e);
        else       c1 += 1ull << (16 * (e - 4));
    }
    unsigned long long s0 = c0, s1 = c1;
#pragma unroll
    for (int o = 1; o < 32; o <<= 1) {
        unsigned long long t0 = __shfl_up_sync(0xffffffffu, s0, o);
        unsigned long long t1 = __shfl_up_sync(0xffffffffu, s1, o);
        if (lane >= o) { s0 += t0; s1 += t1; }
    }
    if (lane == 31) { w0s[tid >> 5] = s0; w1s[tid >> 5] = s1; }
    __syncthreads();
    if (tid < 32) {
        unsigned long long a0 = w0s[tid], a1 = w1s[tid];
#pragma unroll
        for (int o = 1; o < 32; o <<= 1) {
            unsigned long long t0 = __shfl_up_sync(0xffffffffu, a0, o);
            unsigned long long t1 = __shfl_up_sync(0xffffffffu, a1, o);
            if (tid >= o) { a0 += t0; a1 += t1; }
        }
        w0s[tid] = a0; w1s[tid] = a1;
    }
    __syncthreads();
    unsigned long long p0 = s0 - c0, p1 = s1 - c1;   // exclusive within warp
    if (tid >= 32) { p0 += w0s[(tid >> 5) - 1]; p1 += w1s[(tid >> 5) - 1]; }
#pragma unroll
    for (int i = 0; i < 8; i++) {
        int n = tid * 8 + i, e = e8[i];
        int pos;
        if (e < 4) { p0 += 1ull << (16 * e);       pos = (int)((p0 >> (16 * e)) & 0xFFFFull); }
        else       { p1 += 1ull << (16 * (e - 4)); pos = (int)((p1 >> (16 * (e - 4))) & 0xFFFFull); }
        if (pos < CAP) {
            g_comb[n] = e * CAP + pos;       // 1-based pos, slot 0 unused
            g_tok[e * CAP + pos] = n;
        } else {
            g_comb[n] = -1;
        }
    }
}

// ---------------- dispatch scatter + hi/lo split -----------------------------
__global__ void dispatch_kernel(const float* __restrict__ x) {
    int slot = blockIdx.x;
    int t = threadIdx.x;  // 256 threads x 4 floats
    int n = g_tok[slot];
    uint2* dh = reinterpret_cast<uint2*>(g_Ah + (size_t)slot * DIM) + t;
    uint2* dl = reinterpret_cast<uint2*>(g_Al + (size_t)slot * DIM) + t;
    if (n < 0) {
        *dh = make_uint2(0u, 0u);
        *dl = make_uint2(0u, 0u);
    } else {
        float g = g_gate[n];
        float4 v = reinterpret_cast<const float4*>(x + (size_t)n * DIM)[t];
        __nv_bfloat16 h0, l0, h1, l1, h2, l2, h3, l3;
        split_bf16(v.x * g, h0, l0);
        split_bf16(v.y * g, h1, l1);
        split_bf16(v.z * g, h2, l2);
        split_bf16(v.w * g, h3, l3);
        *dh = make_uint2(pk(h0, h1), pk(h2, h3));
        *dl = make_uint2(pk(l0, l1), pk(l2, l3));
    }
}

// ---------------- weight transpose + hi/lo split (vectorized stores) ---------
__global__ void wt_kernel(const float* __restrict__ W,
                          __nv_bfloat16* __restrict__ Bh,
                          __nv_bfloat16* __restrict__ Bl) {
    __shared__ float ts[32][33];
    int e = blockIdx.z;
    int k0 = blockIdx.y * 32, n0 = blockIdx.x * 32;
    int tx = threadIdx.x, ty = threadIdx.y;  // 32 x 8
    const float* Wb = W + (size_t)e * DIM * DIM;
    for (int i = ty; i < 32; i += 8)
        ts[i][tx] = Wb[(size_t)(k0 + i) * DIM + n0 + tx];
    __syncthreads();
    int r  = ty * 4 + (tx >> 3);   // output row (n within tile)
    int kk = (tx & 7) * 4;         // 4 consecutive k per thread
    float v0 = ts[kk + 0][r], v1 = ts[kk + 1][r];
    float v2 = ts[kk + 2][r], v3 = ts[kk + 3][r];
    __nv_bfloat16 h0, l0, h1, l1, h2, l2, h3, l3;
    split_bf16(v0, h0, l0); split_bf16(v1, h1, l1);
    split_bf16(v2, h2, l2); split_bf16(v3, h3, l3);
    size_t o = (size_t)e * DIM * DIM + (size_t)(n0 + r) * DIM + k0 + kk;
    *reinterpret_cast<uint2*>(Bh + o) = make_uint2(pk(h0, h1), pk(h2, h3));
    *reinterpret_cast<uint2*>(Bl + o) = make_uint2(pk(l0, l1), pk(l2, l3));
}

// ---------------- zero rows of dropped tokens --------------------------------
__global__ void dropzero_kernel(float* __restrict__ out) {
    int n = blockIdx.x;
    if (g_comb[n] >= 0) return;
    reinterpret_cast<float4*>(out + (size_t)n * DIM)[threadIdx.x] =
        make_float4(0.f, 0.f, 0.f, 0.f);
}

// ---------------- split-bf16 GEMM via mma.sync (HMMA) -------------------------
// 128x128 CTA tile, BK=32 (64B rows), 3 stages => ~98KB smem => 2 CTAs/SM.
// 3-term: Ah*Bh + Ah*Bl + Al*Bh, fp32 accum in registers.
#define STAGES  3
#define TILEB   8192              // 128 rows x 64B
#define STAGEB  (4 * TILEB)       // Ah, Al, Bh, Bl
#define NCHUNK  32                // K=1024 / BK=32
#define GEMM_SMEM (2048 + STAGES * STAGEB)

// SW64-style swizzle for 64B rows: seg(0..3) ^= (row>>1)&3
#define SWZ64(row, seg) ((row) * 64 + (((seg) ^ (((row) >> 1) & 3)) << 4))

template <bool SPLIT_RELU>
__global__ void __launch_bounds__(256, 2) gemm_mma(
    const __nv_bfloat16* __restrict__ Ah, const __nv_bfloat16* __restrict__ Al,
    const __nv_bfloat16* __restrict__ Bh, const __nv_bfloat16* __restrict__ Bl,
    const float* __restrict__ bias,
    __nv_bfloat16* __restrict__ outH, __nv_bfloat16* __restrict__ outL,
    float* __restrict__ outF) {
    extern __shared__ char smem[];
    uint32_t raw = smem_u32(smem);
    uint32_t tiles = (raw + 512 + 1023) & ~1023u;
    float* sb = reinterpret_cast<float*>(smem + (tiles - 512 - raw)); // 128 floats

    const int tid = threadIdx.x;
    const int lane = tid & 31, wid = tid >> 5;
    const int bx = blockIdx.x, by = blockIdx.y, ex = blockIdx.z;

    const size_t rowA0 = (size_t)ex * 1024 + (size_t)by * 128;
    const size_t rowB0 = (size_t)ex * 1024 + (size_t)bx * 128;
    const char* pA[4] = {
        (const char*)(Ah + rowA0 * DIM), (const char*)(Al + rowA0 * DIM),
        (const char*)(Bh + rowB0 * DIM), (const char*)(Bl + rowB0 * DIM)};

    if (tid < 128) sb[tid] = bias[ex * DIM + bx * 128 + tid];

    auto load_chunk = [&](int c, int s) {
        uint32_t st = tiles + s * STAGEB;
        int kb = c * 64;  // 32 bf16 = 64B per row-chunk
#pragma unroll
        for (int i = 0; i < 8; i++) {
            int g = tid + i * 256;        // 0..2047
            int tile = g >> 9;
            int j = g & 511;
            int row = j >> 2, seg = j & 3;
            uint32_t dst = st + tile * TILEB + SWZ64(row, seg);
            const char* src = pA[tile] + (size_t)row * (DIM * 2) + kb + seg * 16;
            CP_ASYNC16(dst, src);
        }
    };

    load_chunk(0, 0); CP_COMMIT();
    load_chunk(1, 1); CP_COMMIT();

    float acc[4][4][4];
#pragma unroll
    for (int i = 0; i < 4; i++)
#pragma unroll
        for (int j = 0; j < 4; j++)
#pragma unroll
            for (int q = 0; q < 4; q++) acc[i][j][q] = 0.f;

    const int m_off = (wid & 1) * 64;    // warp tile 64x32; warps 2x4
    const int n_off = (wid >> 1) * 32;
    const int grp = lane >> 3, loc = lane & 7;
    const int rowoff_a = (grp & 1) * 8 + loc;
    const int segoff_a = grp >> 1;
    const int rowoff_b = (grp >> 1) * 8 + loc;
    const int segoff_b = grp & 1;

    for (int c = 0; c < NCHUNK; c++) {
        int s = c % STAGES;
        CP_WAIT1();                 // chunk c resident (c+1 still in flight)
        __syncthreads();            // WAR: all warps done reading stage (c+2)%3
        if (c + 2 < NCHUNK) load_chunk(c + 2, (c + 2) % STAGES);
        CP_COMMIT();
        uint32_t st = tiles + s * STAGEB;
#pragma unroll
        for (int ks = 0; ks < 2; ks++) {
            int seg0 = ks * 2;
            uint32_t bH[4][2], bL[4][2];
#pragma unroll
            for (int p = 0; p < 2; p++) {
                int row = n_off + p * 16 + rowoff_b;
                int seg = seg0 + segoff_b;
                uint32_t bd = st + 2 * TILEB + SWZ64(row, seg);
                uint32_t r[4];
                LDSM_X4(r, bd);
                bH[2 * p][0] = r[0]; bH[2 * p][1] = r[1];
                bH[2 * p + 1][0] = r[2]; bH[2 * p + 1][1] = r[3];
                LDSM_X4(r, bd + TILEB);
                bL[2 * p][0] = r[0]; bL[2 * p][1] = r[1];
                bL[2 * p + 1][0] = r[2]; bL[2 * p + 1][1] = r[3];
            }
#pragma unroll
            for (int mt = 0; mt < 4; mt++) {
                int row = m_off + mt * 16 + rowoff_a;
                int seg = seg0 + segoff_a;
                uint32_t ad = st + SWZ64(row, seg);
                uint32_t aH[4], aL[4];
                LDSM_X4(aH, ad);
                LDSM_X4(aL, ad + TILEB);
#pragma unroll
                for (int nt = 0; nt < 4; nt++) {
                    MMA_BF16(acc[mt][nt], aH, bH[nt]);
                    MMA_BF16(acc[mt][nt], aH, bL[nt]);
                    MMA_BF16(acc[mt][nt], aL, bH[nt]);
                }
            }
        }
    }

    // ---- epilogue ----
    const int colb = bx * 128;
#pragma unroll
    for (int mt = 0; mt < 4; mt++) {
        size_t slot0 = rowA0 + m_off + mt * 16 + (lane >> 2);
        size_t slot1 = slot0 + 8;
        int tok0 = 0, tok1 = 0;
        float gt0 = 0.f, gt1 = 0.f;
        if (!SPLIT_RELU) {
            tok0 = g_tok[slot0];
            tok1 = g_tok[slot1];
            gt0 = (tok0 >= 0) ? g_gate[tok0] : 0.f;
            gt1 = (tok1 >= 0) ? g_gate[tok1] : 0.f;
        }
#pragma unroll
        for (int nt = 0; nt < 4; nt++) {
            int cl = n_off + nt * 8 + 2 * (lane & 3);
            float b0 = sb[cl], b1 = sb[cl + 1];
            float v00 = acc[mt][nt][0] + b0, v01 = acc[mt][nt][1] + b1;
            float v10 = acc[mt][nt][2] + b0, v11 = acc[mt][nt][3] + b1;
            if (SPLIT_RELU) {
                v00 = fmaxf(v00, 0.f); v01 = fmaxf(v01, 0.f);
                v10 = fmaxf(v10, 0.f); v11 = fmaxf(v11, 0.f);
                __nv_bfloat16 h0, l0, h1, l1;
                split_bf16(v00, h0, l0); split_bf16(v01, h1, l1);
                *reinterpret_cast<uint32_t*>(outH + slot0 * DIM + colb + cl) = pk(h0, h1);
                *reinterpret_cast<uint32_t*>(outL + slot0 * DIM + colb + cl) = pk(l0, l1);
                split_bf16(v10, h0, l0); split_bf16(v11, h1, l1);
                *reinterpret_cast<uint32_t*>(outH + slot1 * DIM + colb + cl) = pk(h0, h1);
                *reinterpret_cast<uint32_t*>(outL + slot1 * DIM + colb + cl) = pk(l0, l1);
            } else {
                // fused combine: out[token] = gate * (eo + bias)
                if (tok0 >= 0)
                    *reinterpret_cast<float2*>(outF + (size_t)tok0 * DIM + colb + cl) =
                        make_float2(gt0 * v00, gt0 * v01);
                if (tok1 >= 0)
                    *reinterpret_cast<float2*>(outF + (size_t)tok1 * DIM + colb + cl) =
                        make_float2(gt1 * v10, gt1 * v11);
            }
        }
    }
}

// ---------------- launch -------------------------------------------------------
extern "C" void kernel_launch(void* const* d_in, const int* in_sizes, int n_in,
                              void* d_out, int out_size) {
    const float* x  = (const float*)d_in[0];
    const float* Wr = (const float*)d_in[1];
    const float* br = (const float*)d_in[2];
    const float* W1 = (const float*)d_in[3];
    const float* b1 = (const float*)d_in[4];
    const float* W2 = (const float*)d_in[5];
    const float* b2 = (const float*)d_in[6];
    float* out = (float*)d_out;

    void *pAh, *pAl, *pHh, *pHl, *pB1h, *pB1l, *pB2h, *pB2l;
    cudaGetSymbolAddress(&pAh, g_Ah);   cudaGetSymbolAddress(&pAl, g_Al);
    cudaGetSymbolAddress(&pHh, g_Hh);   cudaGetSymbolAddress(&pHl, g_Hl);
    cudaGetSymbolAddress(&pB1h, g_B1h); cudaGetSymbolAddress(&pB1l, g_B1l);
    cudaGetSymbolAddress(&pB2h, g_B2h); cudaGetSymbolAddress(&pB2l, g_B2l);

    cudaFuncSetAttribute(gemm_mma<true>,  cudaFuncAttributeMaxDynamicSharedMemorySize, GEMM_SMEM);
    cudaFuncSetAttribute(gemm_mma<false>, cudaFuncAttributeMaxDynamicSharedMemorySize, GEMM_SMEM);

    router_kernel<<<N_TOK * 32 / 256, 256>>>(x, Wr, br);
    scan_kernel<<<1, 1024>>>();
    dispatch_kernel<<<NEXP * CAP, 256>>>(x);

    dim3 wtg(32, 32, NEXP);
    wt_kernel<<<wtg, dim3(32, 8)>>>(W1, (__nv_bfloat16*)pB1h, (__nv_bfloat16*)pB1l);
    wt_kernel<<<wtg, dim3(32, 8)>>>(W2, (__nv_bfloat16*)pB2h, (__nv_bfloat16*)pB2l);
    dropzero_kernel<<<N_TOK, 256>>>(out);

    dim3 gg(8, 8, NEXP);
    gemm_mma<true><<<gg, 256, GEMM_SMEM>>>(
        (const __nv_bfloat16*)pAh, (const __nv_bfloat16*)pAl,
        (const __nv_bfloat16*)pB1h, (const __nv_bfloat16*)pB1l,
        b1, (__nv_bfloat16*)pHh, (__nv_bfloat16*)pHl, nullptr);
    gemm_mma<false><<<gg, 256, GEMM_SMEM>>>(
        (const __nv_bfloat16*)pHh, (const __nv_bfloat16*)pHl,
        (const __nv_bfloat16*)pB2h, (const __nv_bfloat16*)pB2l,
        b2, nullptr, nullptr, out);
}

// round 6
// speedup vs baseline: 2.4796x; 1.2619x over previous
#include <cuda_runtime.h>
#include <cuda_fp16.h>
#include <cstdint>

#define N_TOK 8192
#define DIM   1024
#define NEXP  8
#define CAP   1024

// ---------------- scratch (device globals; no allocation allowed) ----------
__device__ __half g_Ah[(size_t)N_TOK * DIM];   // expert_in hi plane
__device__ __half g_Al[(size_t)N_TOK * DIM];   // expert_in lo plane
__device__ __half g_Hh[(size_t)N_TOK * DIM];   // hidden hi plane
__device__ __half g_Hl[(size_t)N_TOK * DIM];   // hidden lo plane
__device__ __half g_B1h[(size_t)N_TOK * DIM];  // W1^T hi  [e][n][k]
__device__ __half g_B2h[(size_t)N_TOK * DIM];  // W2^T hi
__device__ int   g_idx[N_TOK];
__device__ float g_gate[N_TOK];
__device__ int   g_comb[N_TOK];
__device__ int   g_tok[NEXP * CAP];

// ---------------- PTX helpers (sm_80-level only) -----------------------------
__device__ __forceinline__ uint32_t smem_u32(const void* p) {
    uint32_t a;
    asm("{ .reg .u64 t; cvta.to.shared.u64 t, %1; cvt.u32.u64 %0, t; }"
        : "=r"(a) : "l"(p));
    return a;
}

#define CP_ASYNC16(dst, src) \
    asm volatile("cp.async.cg.shared.global [%0], [%1], 16;" :: "r"(dst), "l"(src) : "memory")
#define CP_COMMIT() asm volatile("cp.async.commit_group;" ::: "memory")
#define CP_WAIT1()  asm volatile("cp.async.wait_group 1;" ::: "memory")

#define LDSM_X4(r, addr) \
    asm volatile("ldmatrix.sync.aligned.m8n8.x4.shared.b16 {%0,%1,%2,%3}, [%4];" \
        : "=r"((r)[0]), "=r"((r)[1]), "=r"((r)[2]), "=r"((r)[3]) : "r"(addr))

#define MMA_FP16(d, a, b) \
    asm volatile("mma.sync.aligned.m16n8k16.row.col.f32.f16.f16.f32 " \
        "{%0,%1,%2,%3}, {%4,%5,%6,%7}, {%8,%9}, {%0,%1,%2,%3};" \
        : "+f"((d)[0]), "+f"((d)[1]), "+f"((d)[2]), "+f"((d)[3]) \
        : "r"((a)[0]), "r"((a)[1]), "r"((a)[2]), "r"((a)[3]), \
          "r"((b)[0]), "r"((b)[1]))

__device__ __forceinline__ void split_fp16(float v, __half& h, __half& l) {
    h = __float2half_rn(v);
    l = __float2half_rn(v - __half2float(h));
}
__device__ __forceinline__ uint32_t pk(__half a, __half b) {
    return (uint32_t)__half_as_ushort(a) | ((uint32_t)__half_as_ushort(b) << 16);
}

// ---------------- router (+ g_tok init fused): one warp per token -----------
__global__ void router_kernel(const float* __restrict__ x,
                              const float* __restrict__ Wr,
                              const float* __restrict__ br) {
    int gid = blockIdx.x * blockDim.x + threadIdx.x;
    if (gid < NEXP * CAP) g_tok[gid] = -1;
    int gwarp = gid >> 5;
    int lane  = threadIdx.x & 31;
    if (gwarp >= N_TOK) return;
    const float* xr = x + (size_t)gwarp * DIM;
    float acc[NEXP];
#pragma unroll
    for (int e = 0; e < NEXP; e++) acc[e] = 0.f;
    for (int d = lane; d < DIM; d += 32) {
        float xv = xr[d];
        const float* w = Wr + d * NEXP;
#pragma unroll
        for (int e = 0; e < NEXP; e++) acc[e] += xv * w[e];
    }
#pragma unroll
    for (int o = 16; o > 0; o >>= 1)
#pragma unroll
        for (int e = 0; e < NEXP; e++)
            acc[e] += __shfl_xor_sync(0xffffffffu, acc[e], o);
    if (lane == 0) {
        float m = -1e30f; int ai = 0;
#pragma unroll
        for (int e = 0; e < NEXP; e++) {
            acc[e] += br[e];
            if (acc[e] > m) { m = acc[e]; ai = e; }   // strict > keeps first
        }
        float s = 0.f;
#pragma unroll
        for (int e = 0; e < NEXP; e++) s += expf(acc[e] - m);
        g_idx[gwarp]  = ai;
        g_gate[gwarp] = 1.f / s;
    }
}

// ---------------- order-preserving scan: 8 tokens/thread, 3-level shfl ------
__global__ void scan_kernel() {
    __shared__ unsigned long long w0s[32], w1s[32];
    int tid = threadIdx.x;          // 1024 threads
    int lane = tid & 31;
    int e8[8];
    unsigned long long c0 = 0ull, c1 = 0ull;
#pragma unroll
    for (int i = 0; i < 8; i++) {
        int e = g_idx[tid * 8 + i];
        e8[i] = e;
        if (e < 4) c0 += 1ull << (16 * e);
        else       c1 += 1ull << (16 * (e - 4));
    }
    unsigned long long s0 = c0, s1 = c1;
#pragma unroll
    for (int o = 1; o < 32; o <<= 1) {
        unsigned long long t0 = __shfl_up_sync(0xffffffffu, s0, o);
        unsigned long long t1 = __shfl_up_sync(0xffffffffu, s1, o);
        if (lane >= o) { s0 += t0; s1 += t1; }
    }
    if (lane == 31) { w0s[tid >> 5] = s0; w1s[tid >> 5] = s1; }
    __syncthreads();
    if (tid < 32) {
        unsigned long long a0 = w0s[tid], a1 = w1s[tid];
#pragma unroll
        for (int o = 1; o < 32; o <<= 1) {
            unsigned long long t0 = __shfl_up_sync(0xffffffffu, a0, o);
            unsigned long long t1 = __shfl_up_sync(0xffffffffu, a1, o);
            if (tid >= o) { a0 += t0; a1 += t1; }
        }
        w0s[tid] = a0; w1s[tid] = a1;
    }
    __syncthreads();
    unsigned long long p0 = s0 - c0, p1 = s1 - c1;   // exclusive within warp
    if (tid >= 32) { p0 += w0s[(tid >> 5) - 1]; p1 += w1s[(tid >> 5) - 1]; }
#pragma unroll
    for (int i = 0; i < 8; i++) {
        int n = tid * 8 + i, e = e8[i];
        int pos;
        if (e < 4) { p0 += 1ull << (16 * e);       pos = (int)((p0 >> (16 * e)) & 0xFFFFull); }
        else       { p1 += 1ull << (16 * (e - 4)); pos = (int)((p1 >> (16 * (e - 4))) & 0xFFFFull); }
        if (pos < CAP) {
            g_comb[n] = e * CAP + pos;       // 1-based pos, slot 0 unused
            g_tok[e * CAP + pos] = n;
        } else {
            g_comb[n] = -1;
        }
    }
}

// ---------------- dispatch scatter + hi/lo split -----------------------------
__global__ void dispatch_kernel(const float* __restrict__ x) {
    int slot = blockIdx.x;
    int t = threadIdx.x;  // 256 threads x 4 floats
    int n = g_tok[slot];
    uint2* dh = reinterpret_cast<uint2*>(g_Ah + (size_t)slot * DIM) + t;
    uint2* dl = reinterpret_cast<uint2*>(g_Al + (size_t)slot * DIM) + t;
    if (n < 0) {
        *dh = make_uint2(0u, 0u);
        *dl = make_uint2(0u, 0u);
    } else {
        float g = g_gate[n];
        float4 v = reinterpret_cast<const float4*>(x + (size_t)n * DIM)[t];
        __half h0, l0, h1, l1, h2, l2, h3, l3;
        split_fp16(v.x * g, h0, l0);
        split_fp16(v.y * g, h1, l1);
        split_fp16(v.z * g, h2, l2);
        split_fp16(v.w * g, h3, l3);
        *dh = make_uint2(pk(h0, h1), pk(h2, h3));
        *dl = make_uint2(pk(l0, l1), pk(l2, l3));
    }
}

// ---------------- weight transpose (hi plane only) ---------------------------
__global__ void wt_kernel(const float* __restrict__ W,
                          __half* __restrict__ Bh) {
    __shared__ float ts[32][33];
    int e = blockIdx.z;
    int k0 = blockIdx.y * 32, n0 = blockIdx.x * 32;
    int tx = threadIdx.x, ty = threadIdx.y;  // 32 x 8
    const float* Wb = W + (size_t)e * DIM * DIM;
    for (int i = ty; i < 32; i += 8)
        ts[i][tx] = Wb[(size_t)(k0 + i) * DIM + n0 + tx];
    __syncthreads();
    int r  = ty * 4 + (tx >> 3);   // output row (n within tile)
    int kk = (tx & 7) * 4;         // 4 consecutive k per thread
    __half h0 = __float2half_rn(ts[kk + 0][r]);
    __half h1 = __float2half_rn(ts[kk + 1][r]);
    __half h2 = __float2half_rn(ts[kk + 2][r]);
    __half h3 = __float2half_rn(ts[kk + 3][r]);
    size_t o = (size_t)e * DIM * DIM + (size_t)(n0 + r) * DIM + k0 + kk;
    *reinterpret_cast<uint2*>(Bh + o) = make_uint2(pk(h0, h1), pk(h2, h3));
}

// ---------------- zero rows of dropped tokens --------------------------------
__global__ void dropzero_kernel(float* __restrict__ out) {
    int n = blockIdx.x;
    if (g_comb[n] >= 0) return;
    reinterpret_cast<float4*>(out + (size_t)n * DIM)[threadIdx.x] =
        make_float4(0.f, 0.f, 0.f, 0.f);
}

// ---------------- fp16 2-term split GEMM via mma.sync ------------------------
// 128x128 CTA tile, BK=32 (64B rows), 3 stages, 3 planes (Ah, Al, Bh).
// C = Ah*Bh + Al*Bh  (A effective ~22-bit mantissa; error = A*Bl ~ 2^-11 rel)
#define STAGES  3
#define TILEB   8192              // 128 rows x 64B
#define NPLANES 3
#define STAGEB  (NPLANES * TILEB)
#define NCHUNK  32                // K=1024 / BK=32
#define GEMM_SMEM (2048 + STAGES * STAGEB)

// SW64-style swizzle for 64B rows: seg(0..3) ^= (row>>1)&3
#define SWZ64(row, seg) ((row) * 64 + (((seg) ^ (((row) >> 1) & 3)) << 4))

template <bool SPLIT_RELU>
__global__ void __launch_bounds__(256, 2) gemm_mma(
    const __half* __restrict__ Ah, const __half* __restrict__ Al,
    const __half* __restrict__ Bh,
    const float* __restrict__ bias,
    __half* __restrict__ outH, __half* __restrict__ outL,
    float* __restrict__ outF) {
    extern __shared__ char smem[];
    uint32_t raw = smem_u32(smem);
    uint32_t tiles = (raw + 512 + 1023) & ~1023u;
    float* sb = reinterpret_cast<float*>(smem + (tiles - 512 - raw)); // 128 floats

    const int tid = threadIdx.x;
    const int lane = tid & 31, wid = tid >> 5;
    const int bx = blockIdx.x, by = blockIdx.y, ex = blockIdx.z;

    const size_t rowA0 = (size_t)ex * 1024 + (size_t)by * 128;
    const size_t rowB0 = (size_t)ex * 1024 + (size_t)bx * 128;
    const char* pA[3] = {
        (const char*)(Ah + rowA0 * DIM), (const char*)(Al + rowA0 * DIM),
        (const char*)(Bh + rowB0 * DIM)};

    if (tid < 128) sb[tid] = bias[ex * DIM + bx * 128 + tid];

    auto load_chunk = [&](int c, int s) {
        uint32_t st = tiles + s * STAGEB;
        int kb = c * 64;  // 32 fp16 = 64B per row-chunk
#pragma unroll
        for (int i = 0; i < 6; i++) {
            int g = tid + i * 256;        // 0..1535
            int tile = g >> 9;
            int j = g & 511;
            int row = j >> 2, seg = j & 3;
            uint32_t dst = st + tile * TILEB + SWZ64(row, seg);
            const char* src = pA[tile] + (size_t)row * (DIM * 2) + kb + seg * 16;
            CP_ASYNC16(dst, src);
        }
    };

    load_chunk(0, 0); CP_COMMIT();
    load_chunk(1, 1); CP_COMMIT();

    float acc[4][4][4];
#pragma unroll
    for (int i = 0; i < 4; i++)
#pragma unroll
        for (int j = 0; j < 4; j++)
#pragma unroll
            for (int q = 0; q < 4; q++) acc[i][j][q] = 0.f;

    const int m_off = (wid & 1) * 64;    // warp tile 64x32; warps 2x4
    const int n_off = (wid >> 1) * 32;
    const int grp = lane >> 3, loc = lane & 7;
    const int rowoff_a = (grp & 1) * 8 + loc;
    const int segoff_a = grp >> 1;
    const int rowoff_b = (grp >> 1) * 8 + loc;
    const int segoff_b = grp & 1;

    for (int c = 0; c < NCHUNK; c++) {
        int s = c % STAGES;
        CP_WAIT1();                 // chunk c resident (c+1 still in flight)
        __syncthreads();            // WAR: all warps done reading stage (c+2)%3
        if (c + 2 < NCHUNK) load_chunk(c + 2, (c + 2) % STAGES);
        CP_COMMIT();
        uint32_t st = tiles + s * STAGEB;
#pragma unroll
        for (int ks = 0; ks < 2; ks++) {
            int seg0 = ks * 2;
            uint32_t bH[4][2];
#pragma unroll
            for (int p = 0; p < 2; p++) {
                int row = n_off + p * 16 + rowoff_b;
                int seg = seg0 + segoff_b;
                uint32_t bd = st + 2 * TILEB + SWZ64(row, seg);
                uint32_t r[4];
                LDSM_X4(r, bd);
                bH[2 * p][0] = r[0]; bH[2 * p][1] = r[1];
                bH[2 * p + 1][0] = r[2]; bH[2 * p + 1][1] = r[3];
            }
#pragma unroll
            for (int mt = 0; mt < 4; mt++) {
                int row = m_off + mt * 16 + rowoff_a;
                int seg = seg0 + segoff_a;
                uint32_t ad = st + SWZ64(row, seg);
                uint32_t aH[4], aL[4];
                LDSM_X4(aH, ad);
                LDSM_X4(aL, ad + TILEB);
#pragma unroll
                for (int nt = 0; nt < 4; nt++) {
                    MMA_FP16(acc[mt][nt], aH, bH[nt]);
                    MMA_FP16(acc[mt][nt], aL, bH[nt]);
                }
            }
        }
    }

    // ---- epilogue ----
    const int colb = bx * 128;
#pragma unroll
    for (int mt = 0; mt < 4; mt++) {
        size_t slot0 = rowA0 + m_off + mt * 16 + (lane >> 2);
        size_t slot1 = slot0 + 8;
        int tok0 = 0, tok1 = 0;
        float gt0 = 0.f, gt1 = 0.f;
        if (!SPLIT_RELU) {
            tok0 = g_tok[slot0];
            tok1 = g_tok[slot1];
            gt0 = (tok0 >= 0) ? g_gate[tok0] : 0.f;
            gt1 = (tok1 >= 0) ? g_gate[tok1] : 0.f;
        }
#pragma unroll
        for (int nt = 0; nt < 4; nt++) {
            int cl = n_off + nt * 8 + 2 * (lane & 3);
            float b0 = sb[cl], b1 = sb[cl + 1];
            float v00 = acc[mt][nt][0] + b0, v01 = acc[mt][nt][1] + b1;
            float v10 = acc[mt][nt][2] + b0, v11 = acc[mt][nt][3] + b1;
            if (SPLIT_RELU) {
                v00 = fmaxf(v00, 0.f); v01 = fmaxf(v01, 0.f);
                v10 = fmaxf(v10, 0.f); v11 = fmaxf(v11, 0.f);
                __half h0, l0, h1, l1;
                split_fp16(v00, h0, l0); split_fp16(v01, h1, l1);
                *reinterpret_cast<uint32_t*>(outH + slot0 * DIM + colb + cl) = pk(h0, h1);
                *reinterpret_cast<uint32_t*>(outL + slot0 * DIM + colb + cl) = pk(l0, l1);
                split_fp16(v10, h0, l0); split_fp16(v11, h1, l1);
                *reinterpret_cast<uint32_t*>(outH + slot1 * DIM + colb + cl) = pk(h0, h1);
                *reinterpret_cast<uint32_t*>(outL + slot1 * DIM + colb + cl) = pk(l0, l1);
            } else {
                // fused combine: out[token] = gate * (eo + bias)
                if (tok0 >= 0)
                    *reinterpret_cast<float2*>(outF + (size_t)tok0 * DIM + colb + cl) =
                        make_float2(gt0 * v00, gt0 * v01);
                if (tok1 >= 0)
                    *reinterpret_cast<float2*>(outF + (size_t)tok1 * DIM + colb + cl) =
                        make_float2(gt1 * v10, gt1 * v11);
            }
        }
    }
}

// ---------------- launch -------------------------------------------------------
extern "C" void kernel_launch(void* const* d_in, const int* in_sizes, int n_in,
                              void* d_out, int out_size) {
    const float* x  = (const float*)d_in[0];
    const float* Wr = (const float*)d_in[1];
    const float* br = (const float*)d_in[2];
    const float* W1 = (const float*)d_in[3];
    const float* b1 = (const float*)d_in[4];
    const float* W2 = (const float*)d_in[5];
    const float* b2 = (const float*)d_in[6];
    float* out = (float*)d_out;

    void *pAh, *pAl, *pHh, *pHl, *pB1h, *pB2h;
    cudaGetSymbolAddress(&pAh, g_Ah);   cudaGetSymbolAddress(&pAl, g_Al);
    cudaGetSymbolAddress(&pHh, g_Hh);   cudaGetSymbolAddress(&pHl, g_Hl);
    cudaGetSymbolAddress(&pB1h, g_B1h); cudaGetSymbolAddress(&pB2h, g_B2h);

    cudaFuncSetAttribute(gemm_mma<true>,  cudaFuncAttributeMaxDynamicSharedMemorySize, GEMM_SMEM);
    cudaFuncSetAttribute(gemm_mma<false>, cudaFuncAttributeMaxDynamicSharedMemorySize, GEMM_SMEM);

    router_kernel<<<N_TOK * 32 / 256, 256>>>(x, Wr, br);
    scan_kernel<<<1, 1024>>>();
    dispatch_kernel<<<NEXP * CAP, 256>>>(x);

    dim3 wtg(32, 32, NEXP);
    wt_kernel<<<wtg, dim3(32, 8)>>>(W1, (__half*)pB1h);
    wt_kernel<<<wtg, dim3(32, 8)>>>(W2, (__half*)pB2h);
    dropzero_kernel<<<N_TOK, 256>>>(out);

    dim3 gg(8, 8, NEXP);
    gemm_mma<true><<<gg, 256, GEMM_SMEM>>>(
        (const __half*)pAh, (const __half*)pAl, (const __half*)pB1h,
        b1, (__half*)pHh, (__half*)pHl, nullptr);
    gemm_mma<false><<<gg, 256, GEMM_SMEM>>>(
        (const __half*)pHh, (const __half*)pHl, (const __half*)pB2h,
        b2, nullptr, nullptr, out);
}

// round 7
// speedup vs baseline: 3.5963x; 1.4504x over previous
#include <cuda_runtime.h>
#include <cuda_fp16.h>
#include <cstdint>

#define N_TOK 8192
#define DIM   1024
#define NEXP  8
#define CAP   1024

// ---------------- scratch (device globals; no allocation allowed) ----------
__device__ __half g_Ah[(size_t)N_TOK * DIM];   // expert_in fp16
__device__ __half g_Hh[(size_t)N_TOK * DIM];   // hidden fp16
__device__ __half g_B1h[(size_t)N_TOK * DIM];  // W1^T fp16 [e][n][k]
__device__ __half g_B2h[(size_t)N_TOK * DIM];  // W2^T fp16
__device__ int   g_idx[N_TOK];
__device__ float g_gate[N_TOK];
__device__ int   g_comb[N_TOK];
__device__ int   g_tok[NEXP * CAP];

// ---------------- PTX helpers (sm_80-level only) -----------------------------
__device__ __forceinline__ uint32_t smem_u32(const void* p) {
    uint32_t a;
    asm("{ .reg .u64 t; cvta.to.shared.u64 t, %1; cvt.u32.u64 %0, t; }"
        : "=r"(a) : "l"(p));
    return a;
}

#define CP_ASYNC16(dst, src) \
    asm volatile("cp.async.cg.shared.global [%0], [%1], 16;" :: "r"(dst), "l"(src) : "memory")
#define CP_COMMIT() asm volatile("cp.async.commit_group;" ::: "memory")
#define CP_WAIT1()  asm volatile("cp.async.wait_group 1;" ::: "memory")

#define LDSM_X4(r, addr) \
    asm volatile("ldmatrix.sync.aligned.m8n8.x4.shared.b16 {%0,%1,%2,%3}, [%4];" \
        : "=r"((r)[0]), "=r"((r)[1]), "=r"((r)[2]), "=r"((r)[3]) : "r"(addr))

#define MMA_FP16(d, a, b) \
    asm volatile("mma.sync.aligned.m16n8k16.row.col.f32.f16.f16.f32 " \
        "{%0,%1,%2,%3}, {%4,%5,%6,%7}, {%8,%9}, {%0,%1,%2,%3};" \
        : "+f"((d)[0]), "+f"((d)[1]), "+f"((d)[2]), "+f"((d)[3]) \
        : "r"((a)[0]), "r"((a)[1]), "r"((a)[2]), "r"((a)[3]), \
          "r"((b)[0]), "r"((b)[1]))

__device__ __forceinline__ uint32_t pk(__half a, __half b) {
    return (uint32_t)__half_as_ushort(a) | ((uint32_t)__half_as_ushort(b) << 16);
}

// ---------------- router (+ g_tok init fused): one warp per token -----------
__global__ void router_kernel(const float* __restrict__ x,
                              const float* __restrict__ Wr,
                              const float* __restrict__ br) {
    int gid = blockIdx.x * blockDim.x + threadIdx.x;
    if (gid < NEXP * CAP) g_tok[gid] = -1;
    int gwarp = gid >> 5;
    int lane  = threadIdx.x & 31;
    if (gwarp >= N_TOK) return;
    const float* xr = x + (size_t)gwarp * DIM;
    float acc[NEXP];
#pragma unroll
    for (int e = 0; e < NEXP; e++) acc[e] = 0.f;
    for (int d = lane; d < DIM; d += 32) {
        float xv = xr[d];
        const float* w = Wr + d * NEXP;
#pragma unroll
        for (int e = 0; e < NEXP; e++) acc[e] += xv * w[e];
    }
#pragma unroll
    for (int o = 16; o > 0; o >>= 1)
#pragma unroll
        for (int e = 0; e < NEXP; e++)
            acc[e] += __shfl_xor_sync(0xffffffffu, acc[e], o);
    if (lane == 0) {
        float m = -1e30f; int ai = 0;
#pragma unroll
        for (int e = 0; e < NEXP; e++) {
            acc[e] += br[e];
            if (acc[e] > m) { m = acc[e]; ai = e; }   // strict > keeps first
        }
        float s = 0.f;
#pragma unroll
        for (int e = 0; e < NEXP; e++) s += expf(acc[e] - m);
        g_idx[gwarp]  = ai;
        g_gate[gwarp] = 1.f / s;
    }
}

// ---------------- order-preserving scan: 8 tokens/thread, 3-level shfl ------
__global__ void scan_kernel() {
    __shared__ unsigned long long w0s[32], w1s[32];
    int tid = threadIdx.x;          // 1024 threads
    int lane = tid & 31;
    int e8[8];
    unsigned long long c0 = 0ull, c1 = 0ull;
#pragma unroll
    for (int i = 0; i < 8; i++) {
        int e = g_idx[tid * 8 + i];
        e8[i] = e;
        if (e < 4) c0 += 1ull << (16 * e);
        else       c1 += 1ull << (16 * (e - 4));
    }
    unsigned long long s0 = c0, s1 = c1;
#pragma unroll
    for (int o = 1; o < 32; o <<= 1) {
        unsigned long long t0 = __shfl_up_sync(0xffffffffu, s0, o);
        unsigned long long t1 = __shfl_up_sync(0xffffffffu, s1, o);
        if (lane >= o) { s0 += t0; s1 += t1; }
    }
    if (lane == 31) { w0s[tid >> 5] = s0; w1s[tid >> 5] = s1; }
    __syncthreads();
    if (tid < 32) {
        unsigned long long a0 = w0s[tid], a1 = w1s[tid];
#pragma unroll
        for (int o = 1; o < 32; o <<= 1) {
            unsigned long long t0 = __shfl_up_sync(0xffffffffu, a0, o);
            unsigned long long t1 = __shfl_up_sync(0xffffffffu, a1, o);
            if (tid >= o) { a0 += t0; a1 += t1; }
        }
        w0s[tid] = a0; w1s[tid] = a1;
    }
    __syncthreads();
    unsigned long long p0 = s0 - c0, p1 = s1 - c1;   // exclusive within warp
    if (tid >= 32) { p0 += w0s[(tid >> 5) - 1]; p1 += w1s[(tid >> 5) - 1]; }
#pragma unroll
    for (int i = 0; i < 8; i++) {
        int n = tid * 8 + i, e = e8[i];
        int pos;
        if (e < 4) { p0 += 1ull << (16 * e);       pos = (int)((p0 >> (16 * e)) & 0xFFFFull); }
        else       { p1 += 1ull << (16 * (e - 4)); pos = (int)((p1 >> (16 * (e - 4))) & 0xFFFFull); }
        if (pos < CAP) {
            g_comb[n] = e * CAP + pos;       // 1-based pos, slot 0 unused
            g_tok[e * CAP + pos] = n;
        } else {
            g_comb[n] = -1;
        }
    }
}

// ---------------- dispatch scatter (gate * x -> fp16) ------------------------
__global__ void dispatch_kernel(const float* __restrict__ x) {
    int slot = blockIdx.x;
    int t = threadIdx.x;  // 256 threads x 4 floats
    int n = g_tok[slot];
    uint2* dh = reinterpret_cast<uint2*>(g_Ah + (size_t)slot * DIM) + t;
    if (n < 0) {
        *dh = make_uint2(0u, 0u);
    } else {
        float g = g_gate[n];
        float4 v = reinterpret_cast<const float4*>(x + (size_t)n * DIM)[t];
        *dh = make_uint2(pk(__float2half_rn(v.x * g), __float2half_rn(v.y * g)),
                         pk(__float2half_rn(v.z * g), __float2half_rn(v.w * g)));
    }
}

// ---------------- weight transpose fp32[k][n] -> fp16[n][k], 64x64 tiles -----
__global__ void __launch_bounds__(256) wt_kernel(const float* __restrict__ W,
                                                 __half* __restrict__ Bh) {
    __shared__ float ts[64][65];
    int e = blockIdx.z;
    int k0 = blockIdx.y * 64, n0 = blockIdx.x * 64;
    int t = threadIdx.x;
    const float* Wb = W + (size_t)e * DIM * DIM;
    // load 64x64 fp32, float4-coalesced: 16 threads/row, 4 rows per pass
    int lr = t >> 4, lc = (t & 15) * 4;
#pragma unroll
    for (int i = 0; i < 4; i++) {
        int kr = lr + i * 16;
        float4 v = *reinterpret_cast<const float4*>(Wb + (size_t)(k0 + kr) * DIM + n0 + lc);
        ts[kr][lc + 0] = v.x; ts[kr][lc + 1] = v.y;
        ts[kr][lc + 2] = v.z; ts[kr][lc + 3] = v.w;
    }
    __syncthreads();
    // store: each thread 1 output row-segment: 16 k-values -> 32B
    int r  = t >> 2;             // n within tile
    int kk = (t & 3) * 16;       // k start
    uint32_t w[8];
#pragma unroll
    for (int q = 0; q < 8; q++)
        w[q] = pk(__float2half_rn(ts[kk + 2 * q][r]), __float2half_rn(ts[kk + 2 * q + 1][r]));
    size_t o = (size_t)e * DIM * DIM + (size_t)(n0 + r) * DIM + k0 + kk;
    *reinterpret_cast<uint4*>(g_B1h + 0) = *reinterpret_cast<uint4*>(g_B1h + 0); // no-op keep type
    *reinterpret_cast<uint4*>(Bh + o)     = make_uint4(w[0], w[1], w[2], w[3]);
    *reinterpret_cast<uint4*>(Bh + o + 8) = make_uint4(w[4], w[5], w[6], w[7]);
}

// ---------------- zero rows of dropped tokens --------------------------------
__global__ void dropzero_kernel(float* __restrict__ out) {
    int n = blockIdx.x;
    if (g_comb[n] >= 0) return;
    reinterpret_cast<float4*>(out + (size_t)n * DIM)[threadIdx.x] =
        make_float4(0.f, 0.f, 0.f, 0.f);
}

// ---------------- fp16 GEMM via mma.sync (single plane) ----------------------
// 128x128 CTA tile, BK=32 (64B rows), 3 stages, 2 planes (A, B) = 48KB smem.
#define STAGES  3
#define TILEB   8192              // 128 rows x 64B
#define NPLANES 2
#define STAGEB  (NPLANES * TILEB)
#define NCHUNK  32                // K=1024 / BK=32
#define GEMM_SMEM (2048 + STAGES * STAGEB)

// SW64-style swizzle for 64B rows: seg(0..3) ^= (row>>1)&3
#define SWZ64(row, seg) ((row) * 64 + (((seg) ^ (((row) >> 1) & 3)) << 4))

template <bool SPLIT_RELU>
__global__ void __launch_bounds__(256, 2) gemm_mma(
    const __half* __restrict__ Ah, const __half* __restrict__ Bh,
    const float* __restrict__ bias,
    __half* __restrict__ outH, float* __restrict__ outF) {
    extern __shared__ char smem[];
    uint32_t raw = smem_u32(smem);
    uint32_t tiles = (raw + 512 + 1023) & ~1023u;
    float* sb = reinterpret_cast<float*>(smem + (tiles - 512 - raw)); // 128 floats

    const int tid = threadIdx.x;
    const int lane = tid & 31, wid = tid >> 5;
    const int bx = blockIdx.x, by = blockIdx.y, ex = blockIdx.z;

    const size_t rowA0 = (size_t)ex * 1024 + (size_t)by * 128;
    const size_t rowB0 = (size_t)ex * 1024 + (size_t)bx * 128;
    const char* pA[2] = {
        (const char*)(Ah + rowA0 * DIM), (const char*)(Bh + rowB0 * DIM)};

    if (tid < 128) sb[tid] = bias[ex * DIM + bx * 128 + tid];

    auto load_chunk = [&](int c, int s) {
        uint32_t st = tiles + s * STAGEB;
        int kb = c * 64;  // 32 fp16 = 64B per row-chunk
#pragma unroll
        for (int i = 0; i < 4; i++) {
            int g = tid + i * 256;        // 0..1023
            int tile = g >> 9;
            int j = g & 511;
            int row = j >> 2, seg = j & 3;
            uint32_t dst = st + tile * TILEB + SWZ64(row, seg);
            const char* src = pA[tile] + (size_t)row * (DIM * 2) + kb + seg * 16;
            CP_ASYNC16(dst, src);
        }
    };

    load_chunk(0, 0); CP_COMMIT();
    load_chunk(1, 1); CP_COMMIT();

    float acc[4][4][4];
#pragma unroll
    for (int i = 0; i < 4; i++)
#pragma unroll
        for (int j = 0; j < 4; j++)
#pragma unroll
            for (int q = 0; q < 4; q++) acc[i][j][q] = 0.f;

    const int m_off = (wid & 1) * 64;    // warp tile 64x32; warps 2x4
    const int n_off = (wid >> 1) * 32;
    const int grp = lane >> 3, loc = lane & 7;
    const int rowoff_a = (grp & 1) * 8 + loc;
    const int segoff_a = grp >> 1;
    const int rowoff_b = (grp >> 1) * 8 + loc;
    const int segoff_b = grp & 1;

    for (int c = 0; c < NCHUNK; c++) {
        int s = c % STAGES;
        CP_WAIT1();                 // chunk c resident (c+1 still in flight)
        __syncthreads();            // WAR: all warps done reading stage (c+2)%3
        if (c + 2 < NCHUNK) load_chunk(c + 2, (c + 2) % STAGES);
        CP_COMMIT();
        uint32_t st = tiles + s * STAGEB;
#pragma unroll
        for (int ks = 0; ks < 2; ks++) {
            int seg0 = ks * 2;
            uint32_t bH[4][2];
#pragma unroll
            for (int p = 0; p < 2; p++) {
                int row = n_off + p * 16 + rowoff_b;
                int seg = seg0 + segoff_b;
                uint32_t bd = st + TILEB + SWZ64(row, seg);
                uint32_t r[4];
                LDSM_X4(r, bd);
                bH[2 * p][0] = r[0]; bH[2 * p][1] = r[1];
                bH[2 * p + 1][0] = r[2]; bH[2 * p + 1][1] = r[3];
            }
#pragma unroll
            for (int mt = 0; mt < 4; mt++) {
                int row = m_off + mt * 16 + rowoff_a;
                int seg = seg0 + segoff_a;
                uint32_t ad = st + SWZ64(row, seg);
                uint32_t aH[4];
                LDSM_X4(aH, ad);
#pragma unroll
                for (int nt = 0; nt < 4; nt++)
                    MMA_FP16(acc[mt][nt], aH, bH[nt]);
            }
        }
    }

    // ---- epilogue ----
    const int colb = bx * 128;
#pragma unroll
    for (int mt = 0; mt < 4; mt++) {
        size_t slot0 = rowA0 + m_off + mt * 16 + (lane >> 2);
        size_t slot1 = slot0 + 8;
        int tok0 = 0, tok1 = 0;
        float gt0 = 0.f, gt1 = 0.f;
        if (!SPLIT_RELU) {
            tok0 = g_tok[slot0];
            tok1 = g_tok[slot1];
            gt0 = (tok0 >= 0) ? g_gate[tok0] : 0.f;
            gt1 = (tok1 >= 0) ? g_gate[tok1] : 0.f;
        }
#pragma unroll
        for (int nt = 0; nt < 4; nt++) {
            int cl = n_off + nt * 8 + 2 * (lane & 3);
            float b0 = sb[cl], b1 = sb[cl + 1];
            float v00 = acc[mt][nt][0] + b0, v01 = acc[mt][nt][1] + b1;
            float v10 = acc[mt][nt][2] + b0, v11 = acc[mt][nt][3] + b1;
            if (SPLIT_RELU) {
                v00 = fmaxf(v00, 0.f); v01 = fmaxf(v01, 0.f);
                v10 = fmaxf(v10, 0.f); v11 = fmaxf(v11, 0.f);
                *reinterpret_cast<uint32_t*>(outH + slot0 * DIM + colb + cl) =
                    pk(__float2half_rn(v00), __float2half_rn(v01));
                *reinterpret_cast<uint32_t*>(outH + slot1 * DIM + colb + cl) =
                    pk(__float2half_rn(v10), __float2half_rn(v11));
            } else {
                // fused combine: out[token] = gate * (eo + bias)
                if (tok0 >= 0)
                    *reinterpret_cast<float2*>(outF + (size_t)tok0 * DIM + colb + cl) =
                        make_float2(gt0 * v00, gt0 * v01);
                if (tok1 >= 0)
                    *reinterpret_cast<float2*>(outF + (size_t)tok1 * DIM + colb + cl) =
                        make_float2(gt1 * v10, gt1 * v11);
            }
        }
    }
}

// ---------------- launch -------------------------------------------------------
extern "C" void kernel_launch(void* const* d_in, const int* in_sizes, int n_in,
                              void* d_out, int out_size) {
    const float* x  = (const float*)d_in[0];
    const float* Wr = (const float*)d_in[1];
    const float* br = (const float*)d_in[2];
    const float* W1 = (const float*)d_in[3];
    const float* b1 = (const float*)d_in[4];
    const float* W2 = (const float*)d_in[5];
    const float* b2 = (const float*)d_in[6];
    float* out = (float*)d_out;

    void *pAh, *pHh, *pB1h, *pB2h;
    cudaGetSymbolAddress(&pAh, g_Ah);
    cudaGetSymbolAddress(&pHh, g_Hh);
    cudaGetSymbolAddress(&pB1h, g_B1h);
    cudaGetSymbolAddress(&pB2h, g_B2h);

    cudaFuncSetAttribute(gemm_mma<true>,  cudaFuncAttributeMaxDynamicSharedMemorySize, GEMM_SMEM);
    cudaFuncSetAttribute(gemm_mma<false>, cudaFuncAttributeMaxDynamicSharedMemorySize, GEMM_SMEM);

    router_kernel<<<N_TOK * 32 / 256, 256>>>(x, Wr, br);
    scan_kernel<<<1, 1024>>>();
    dispatch_kernel<<<NEXP * CAP, 256>>>(x);

    dim3 wtg(16, 16, NEXP);
    wt_kernel<<<wtg, 256>>>(W1, (__half*)pB1h);
    wt_kernel<<<wtg, 256>>>(W2, (__half*)pB2h);
    dropzero_kernel<<<N_TOK, 256>>>(out);

    dim3 gg(8, 8, NEXP);
    gemm_mma<true><<<gg, 256, GEMM_SMEM>>>(
        (const __half*)pAh, (const __half*)pB1h, b1, (__half*)pHh, nullptr);
    gemm_mma<false><<<gg, 256, GEMM_SMEM>>>(
        (const __half*)pHh, (const __half*)pB2h, b2, nullptr, out);
}

// round 8
// speedup vs baseline: 3.6446x; 1.0134x over previous
#include <cuda_runtime.h>
#include <cuda_fp16.h>
#include <cstdint>

#define N_TOK 8192
#define DIM   1024
#define NEXP  8
#define CAP   1024

// ---------------- scratch (device globals; no allocation allowed) ----------
__device__ __half g_Ah[(size_t)N_TOK * DIM];   // expert_in fp16
__device__ __half g_Hh[(size_t)N_TOK * DIM];   // hidden fp16
__device__ __half g_B1h[(size_t)N_TOK * DIM];  // W1^T fp16 [e][n][k]
__device__ __half g_B2h[(size_t)N_TOK * DIM];  // W2^T fp16
__device__ int   g_idx[N_TOK];
__device__ float g_gate[N_TOK];
__device__ int   g_comb[N_TOK];
__device__ int   g_tok[NEXP * CAP];

// ---------------- PTX helpers (sm_80-level only) -----------------------------
__device__ __forceinline__ uint32_t smem_u32(const void* p) {
    uint32_t a;
    asm("{ .reg .u64 t; cvta.to.shared.u64 t, %1; cvt.u32.u64 %0, t; }"
        : "=r"(a) : "l"(p));
    return a;
}

#define CP_ASYNC16(dst, src) \
    asm volatile("cp.async.cg.shared.global [%0], [%1], 16;" :: "r"(dst), "l"(src) : "memory")
#define CP_COMMIT() asm volatile("cp.async.commit_group;" ::: "memory")
#define CP_WAIT1()  asm volatile("cp.async.wait_group 1;" ::: "memory")

#define LDSM_X4(r, addr) \
    asm volatile("ldmatrix.sync.aligned.m8n8.x4.shared.b16 {%0,%1,%2,%3}, [%4];" \
        : "=r"((r)[0]), "=r"((r)[1]), "=r"((r)[2]), "=r"((r)[3]) : "r"(addr))

#define MMA_FP16(d, a, b) \
    asm volatile("mma.sync.aligned.m16n8k16.row.col.f32.f16.f16.f32 " \
        "{%0,%1,%2,%3}, {%4,%5,%6,%7}, {%8,%9}, {%0,%1,%2,%3};" \
        : "+f"((d)[0]), "+f"((d)[1]), "+f"((d)[2]), "+f"((d)[3]) \
        : "r"((a)[0]), "r"((a)[1]), "r"((a)[2]), "r"((a)[3]), \
          "r"((b)[0]), "r"((b)[1]))

__device__ __forceinline__ uint32_t pk(__half a, __half b) {
    return (uint32_t)__half_as_ushort(a) | ((uint32_t)__half_as_ushort(b) << 16);
}

// ---------------- router (+ g_tok init fused): one warp per token -----------
__global__ void router_kernel(const float* __restrict__ x,
                              const float* __restrict__ Wr,
                              const float* __restrict__ br) {
    int gid = blockIdx.x * blockDim.x + threadIdx.x;
    if (gid < NEXP * CAP) g_tok[gid] = -1;
    int gwarp = gid >> 5;
    int lane  = threadIdx.x & 31;
    if (gwarp >= N_TOK) return;
    const float* xr = x + (size_t)gwarp * DIM;
    float acc[NEXP];
#pragma unroll
    for (int e = 0; e < NEXP; e++) acc[e] = 0.f;
    for (int d = lane; d < DIM; d += 32) {
        float xv = xr[d];
        const float* w = Wr + d * NEXP;
#pragma unroll
        for (int e = 0; e < NEXP; e++) acc[e] += xv * w[e];
    }
#pragma unroll
    for (int o = 16; o > 0; o >>= 1)
#pragma unroll
        for (int e = 0; e < NEXP; e++)
            acc[e] += __shfl_xor_sync(0xffffffffu, acc[e], o);
    if (lane == 0) {
        float m = -1e30f; int ai = 0;
#pragma unroll
        for (int e = 0; e < NEXP; e++) {
            acc[e] += br[e];
            if (acc[e] > m) { m = acc[e]; ai = e; }   // strict > keeps first
        }
        float s = 0.f;
#pragma unroll
        for (int e = 0; e < NEXP; e++) s += expf(acc[e] - m);
        g_idx[gwarp]  = ai;
        g_gate[gwarp] = 1.f / s;
    }
}

// ---------------- order-preserving scan: 8 tokens/thread, 3-level shfl ------
__global__ void scan_kernel() {
    __shared__ unsigned long long w0s[32], w1s[32];
    int tid = threadIdx.x;          // 1024 threads
    int lane = tid & 31;
    int e8[8];
    unsigned long long c0 = 0ull, c1 = 0ull;
#pragma unroll
    for (int i = 0; i < 8; i++) {
        int e = g_idx[tid * 8 + i];
        e8[i] = e;
        if (e < 4) c0 += 1ull << (16 * e);
        else       c1 += 1ull << (16 * (e - 4));
    }
    unsigned long long s0 = c0, s1 = c1;
#pragma unroll
    for (int o = 1; o < 32; o <<= 1) {
        unsigned long long t0 = __shfl_up_sync(0xffffffffu, s0, o);
        unsigned long long t1 = __shfl_up_sync(0xffffffffu, s1, o);
        if (lane >= o) { s0 += t0; s1 += t1; }
    }
    if (lane == 31) { w0s[tid >> 5] = s0; w1s[tid >> 5] = s1; }
    __syncthreads();
    if (tid < 32) {
        unsigned long long a0 = w0s[tid], a1 = w1s[tid];
#pragma unroll
        for (int o = 1; o < 32; o <<= 1) {
            unsigned long long t0 = __shfl_up_sync(0xffffffffu, a0, o);
            unsigned long long t1 = __shfl_up_sync(0xffffffffu, a1, o);
            if (tid >= o) { a0 += t0; a1 += t1; }
        }
        w0s[tid] = a0; w1s[tid] = a1;
    }
    __syncthreads();
    unsigned long long p0 = s0 - c0, p1 = s1 - c1;   // exclusive within warp
    if (tid >= 32) { p0 += w0s[(tid >> 5) - 1]; p1 += w1s[(tid >> 5) - 1]; }
#pragma unroll
    for (int i = 0; i < 8; i++) {
        int n = tid * 8 + i, e = e8[i];
        int pos;
        if (e < 4) { p0 += 1ull << (16 * e);       pos = (int)((p0 >> (16 * e)) & 0xFFFFull); }
        else       { p1 += 1ull << (16 * (e - 4)); pos = (int)((p1 >> (16 * (e - 4))) & 0xFFFFull); }
        if (pos < CAP) {
            g_comb[n] = e * CAP + pos;       // 1-based pos, slot 0 unused
            g_tok[e * CAP + pos] = n;
        } else {
            g_comb[n] = -1;
        }
    }
}

// -------- dispatch scatter (gate*x -> fp16) + dropped-token zeroing ----------
__global__ void dispatch_kernel(const float* __restrict__ x,
                                float* __restrict__ out) {
    int b = blockIdx.x;
    int t = threadIdx.x;  // 256 threads x 4 elements
    if (b < NEXP * CAP) {
        int n = g_tok[b];
        uint2* dh = reinterpret_cast<uint2*>(g_Ah + (size_t)b * DIM) + t;
        if (n < 0) {
            *dh = make_uint2(0u, 0u);
        } else {
            float g = g_gate[n];
            float4 v = reinterpret_cast<const float4*>(x + (size_t)n * DIM)[t];
            *dh = make_uint2(pk(__float2half_rn(v.x * g), __float2half_rn(v.y * g)),
                             pk(__float2half_rn(v.z * g), __float2half_rn(v.w * g)));
        }
    } else {
        int n = b - NEXP * CAP;
        if (g_comb[n] < 0)
            reinterpret_cast<float4*>(out + (size_t)n * DIM)[t] =
                make_float4(0.f, 0.f, 0.f, 0.f);
    }
}

// ---------------- weight transpose fp32[k][n] -> fp16[n][k], 64x64 tiles -----
__global__ void __launch_bounds__(256) wt_kernel(const float* __restrict__ W,
                                                 __half* __restrict__ Bh) {
    __shared__ float ts[64][65];
    int e = blockIdx.z;
    int k0 = blockIdx.y * 64, n0 = blockIdx.x * 64;
    int t = threadIdx.x;
    const float* Wb = W + (size_t)e * DIM * DIM;
    // load 64x64 fp32, float4-coalesced: 16 threads/row, 4 rows per pass
    int lr = t >> 4, lc = (t & 15) * 4;
#pragma unroll
    for (int i = 0; i < 4; i++) {
        int kr = lr + i * 16;
        float4 v = *reinterpret_cast<const float4*>(Wb + (size_t)(k0 + kr) * DIM + n0 + lc);
        ts[kr][lc + 0] = v.x; ts[kr][lc + 1] = v.y;
        ts[kr][lc + 2] = v.z; ts[kr][lc + 3] = v.w;
    }
    __syncthreads();
    // store: each thread 1 output row-segment: 16 k-values -> 32B
    int r  = t >> 2;             // n within tile
    int kk = (t & 3) * 16;       // k start
    uint32_t w[8];
#pragma unroll
    for (int q = 0; q < 8; q++)
        w[q] = pk(__float2half_rn(ts[kk + 2 * q][r]), __float2half_rn(ts[kk + 2 * q + 1][r]));
    size_t o = (size_t)e * DIM * DIM + (size_t)(n0 + r) * DIM + k0 + kk;
    *reinterpret_cast<uint4*>(Bh + o)     = make_uint4(w[0], w[1], w[2], w[3]);
    *reinterpret_cast<uint4*>(Bh + o + 8) = make_uint4(w[4], w[5], w[6], w[7]);
}

// ---------------- fp16 GEMM via mma.sync (single plane) ----------------------
// 128x128 CTA tile, BK=32 (64B rows), 3 stages, 2 planes (A, B) = 48KB smem.
#define STAGES  3
#define TILEB   8192              // 128 rows x 64B
#define NPLANES 2
#define STAGEB  (NPLANES * TILEB)
#define NCHUNK  32                // K=1024 / BK=32
#define GEMM_SMEM (2048 + STAGES * STAGEB)

// SW64-style swizzle for 64B rows: seg(0..3) ^= (row>>1)&3
#define SWZ64(row, seg) ((row) * 64 + (((seg) ^ (((row) >> 1) & 3)) << 4))

template <bool SPLIT_RELU>
__global__ void __launch_bounds__(256, 2) gemm_mma(
    const __half* __restrict__ Ah, const __half* __restrict__ Bh,
    const float* __restrict__ bias,
    __half* __restrict__ outH, float* __restrict__ outF) {
    extern __shared__ char smem[];
    uint32_t raw = smem_u32(smem);
    uint32_t tiles = (raw + 512 + 1023) & ~1023u;
    float* sb = reinterpret_cast<float*>(smem + (tiles - 512 - raw)); // 128 floats

    const int tid = threadIdx.x;
    const int lane = tid & 31, wid = tid >> 5;
    const int bx = blockIdx.x, by = blockIdx.y, ex = blockIdx.z;

    const size_t rowA0 = (size_t)ex * 1024 + (size_t)by * 128;
    const size_t rowB0 = (size_t)ex * 1024 + (size_t)bx * 128;
    const char* pA[2] = {
        (const char*)(Ah + rowA0 * DIM), (const char*)(Bh + rowB0 * DIM)};

    if (tid < 128) sb[tid] = bias[ex * DIM + bx * 128 + tid];

    auto load_chunk = [&](int c, int s) {
        uint32_t st = tiles + s * STAGEB;
        int kb = c * 64;  // 32 fp16 = 64B per row-chunk
#pragma unroll
        for (int i = 0; i < 4; i++) {
            int g = tid + i * 256;        // 0..1023
            int tile = g >> 9;
            int j = g & 511;
            int row = j >> 2, seg = j & 3;
            uint32_t dst = st + tile * TILEB + SWZ64(row, seg);
            const char* src = pA[tile] + (size_t)row * (DIM * 2) + kb + seg * 16;
            CP_ASYNC16(dst, src);
        }
    };

    load_chunk(0, 0); CP_COMMIT();
    load_chunk(1, 1); CP_COMMIT();

    float acc[4][4][4];
#pragma unroll
    for (int i = 0; i < 4; i++)
#pragma unroll
        for (int j = 0; j < 4; j++)
#pragma unroll
            for (int q = 0; q < 4; q++) acc[i][j][q] = 0.f;

    const int m_off = (wid & 1) * 64;    // warp tile 64x32; warps 2x4
    const int n_off = (wid >> 1) * 32;
    const int grp = lane >> 3, loc = lane & 7;
    const int rowoff_a = (grp & 1) * 8 + loc;
    const int segoff_a = grp >> 1;
    const int rowoff_b = (grp >> 1) * 8 + loc;
    const int segoff_b = grp & 1;

    for (int c = 0; c < NCHUNK; c++) {
        int s = c % STAGES;
        CP_WAIT1();                 // chunk c resident (c+1 still in flight)
        __syncthreads();            // WAR: all warps done reading stage (c+2)%3
        if (c + 2 < NCHUNK) load_chunk(c + 2, (c + 2) % STAGES);
        CP_COMMIT();
        uint32_t st = tiles + s * STAGEB;
#pragma unroll
        for (int ks = 0; ks < 2; ks++) {
            int seg0 = ks * 2;
            uint32_t bH[4][2];
#pragma unroll
            for (int p = 0; p < 2; p++) {
                int row = n_off + p * 16 + rowoff_b;
                int seg = seg0 + segoff_b;
                uint32_t bd = st + TILEB + SWZ64(row, seg);
                uint32_t r[4];
                LDSM_X4(r, bd);
                bH[2 * p][0] = r[0]; bH[2 * p][1] = r[1];
                bH[2 * p + 1][0] = r[2]; bH[2 * p + 1][1] = r[3];
            }
#pragma unroll
            for (int mt = 0; mt < 4; mt++) {
                int row = m_off + mt * 16 + rowoff_a;
                int seg = seg0 + segoff_a;
                uint32_t ad = st + SWZ64(row, seg);
                uint32_t aH[4];
                LDSM_X4(aH, ad);
#pragma unroll
                for (int nt = 0; nt < 4; nt++)
                    MMA_FP16(acc[mt][nt], aH, bH[nt]);
            }
        }
    }

    // ---- epilogue ----
    const int colb = bx * 128;
#pragma unroll
    for (int mt = 0; mt < 4; mt++) {
        size_t slot0 = rowA0 + m_off + mt * 16 + (lane >> 2);
        size_t slot1 = slot0 + 8;
        int tok0 = 0, tok1 = 0;
        float gt0 = 0.f, gt1 = 0.f;
        if (!SPLIT_RELU) {
            tok0 = g_tok[slot0];
            tok1 = g_tok[slot1];
            gt0 = (tok0 >= 0) ? g_gate[tok0] : 0.f;
            gt1 = (tok1 >= 0) ? g_gate[tok1] : 0.f;
        }
#pragma unroll
        for (int nt = 0; nt < 4; nt++) {
            int cl = n_off + nt * 8 + 2 * (lane & 3);
            float b0 = sb[cl], b1 = sb[cl + 1];
            float v00 = acc[mt][nt][0] + b0, v01 = acc[mt][nt][1] + b1;
            float v10 = acc[mt][nt][2] + b0, v11 = acc[mt][nt][3] + b1;
            if (SPLIT_RELU) {
                v00 = fmaxf(v00, 0.f); v01 = fmaxf(v01, 0.f);
                v10 = fmaxf(v10, 0.f); v11 = fmaxf(v11, 0.f);
                *reinterpret_cast<uint32_t*>(outH + slot0 * DIM + colb + cl) =
                    pk(__float2half_rn(v00), __float2half_rn(v01));
                *reinterpret_cast<uint32_t*>(outH + slot1 * DIM + colb + cl) =
                    pk(__float2half_rn(v10), __float2half_rn(v11));
            } else {
                // fused combine: out[token] = gate * (eo + bias)
                if (tok0 >= 0)
                    *reinterpret_cast<float2*>(outF + (size_t)tok0 * DIM + colb + cl) =
                        make_float2(gt0 * v00, gt0 * v01);
                if (tok1 >= 0)
                    *reinterpret_cast<float2*>(outF + (size_t)tok1 * DIM + colb + cl) =
                        make_float2(gt1 * v10, gt1 * v11);
            }
        }
    }
}

// ---------------- launch -------------------------------------------------------
extern "C" void kernel_launch(void* const* d_in, const int* in_sizes, int n_in,
                              void* d_out, int out_size) {
    const float* x  = (const float*)d_in[0];
    const float* Wr = (const float*)d_in[1];
    const float* br = (const float*)d_in[2];
    const float* W1 = (const float*)d_in[3];
    const float* b1 = (const float*)d_in[4];
    const float* W2 = (const float*)d_in[5];
    const float* b2 = (const float*)d_in[6];
    float* out = (float*)d_out;

    void *pAh, *pHh, *pB1h, *pB2h;
    cudaGetSymbolAddress(&pAh, g_Ah);
    cudaGetSymbolAddress(&pHh, g_Hh);
    cudaGetSymbolAddress(&pB1h, g_B1h);
    cudaGetSymbolAddress(&pB2h, g_B2h);

    cudaFuncSetAttribute(gemm_mma<true>,  cudaFuncAttributeMaxDynamicSharedMemorySize, GEMM_SMEM);
    cudaFuncSetAttribute(gemm_mma<false>, cudaFuncAttributeMaxDynamicSharedMemorySize, GEMM_SMEM);

    // side stream + events (created once; host resources only, device work is
    // identical on every call -> deterministic & graph-capturable fork/join)
    static cudaStream_t s_side = nullptr;
    static cudaEvent_t  ev_root = nullptr, ev_wt = nullptr;
    if (s_side == nullptr) {
        cudaStreamCreateWithFlags(&s_side, cudaStreamNonBlocking);
        cudaEventCreateWithFlags(&ev_root, cudaEventDisableTiming);
        cudaEventCreateWithFlags(&ev_wt,   cudaEventDisableTiming);
    }

    // fork: weight conversion runs concurrently with router/scan/dispatch
    cudaEventRecord(ev_root, 0);
    cudaStreamWaitEvent(s_side, ev_root, 0);
    dim3 wtg(16, 16, NEXP);
    wt_kernel<<<wtg, 256, 0, s_side>>>(W1, (__half*)pB1h);
    wt_kernel<<<wtg, 256, 0, s_side>>>(W2, (__half*)pB2h);
    cudaEventRecord(ev_wt, s_side);

    // main chain
    router_kernel<<<N_TOK * 32 / 256, 256>>>(x, Wr, br);
    scan_kernel<<<1, 1024>>>();
    dispatch_kernel<<<2 * NEXP * CAP, 256>>>(x, out);

    // join: GEMMs need converted weights
    cudaStreamWaitEvent(0, ev_wt, 0);

    dim3 gg(8, 8, NEXP);
    gemm_mma<true><<<gg, 256, GEMM_SMEM>>>(
        (const __half*)pAh, (const __half*)pB1h, b1, (__half*)pHh, nullptr);
    gemm_mma<false><<<gg, 256, GEMM_SMEM>>>(
        (const __half*)pHh, (const __half*)pB2h, b2, nullptr, out);
}

// round 9
// speedup vs baseline: 3.7922x; 1.0405x over previous
#include <cuda_runtime.h>
#include <cuda_fp16.h>
#include <cstdint>

#define N_TOK 8192
#define DIM   1024
#define NEXP  8
#define CAP   1024

// ---------------- scratch (device globals; no allocation allowed) ----------
__device__ __half g_Ah[(size_t)N_TOK * DIM];   // expert_in fp16
__device__ __half g_Hh[(size_t)N_TOK * DIM];   // hidden fp16
__device__ __half g_B1h[(size_t)N_TOK * DIM];  // W1^T fp16 [e][n][k]
__device__ __half g_B2h[(size_t)N_TOK * DIM];  // W2^T fp16
__device__ int   g_idx[N_TOK];
__device__ float g_gate[N_TOK];
__device__ int   g_comb[N_TOK];
__device__ int   g_tok[NEXP * CAP];

// ---------------- PTX helpers (sm_80-level only) -----------------------------
__device__ __forceinline__ uint32_t smem_u32(const void* p) {
    uint32_t a;
    asm("{ .reg .u64 t; cvta.to.shared.u64 t, %1; cvt.u32.u64 %0, t; }"
        : "=r"(a) : "l"(p));
    return a;
}

#define CP_ASYNC16(dst, src) \
    asm volatile("cp.async.cg.shared.global [%0], [%1], 16;" :: "r"(dst), "l"(src) : "memory")
#define CP_COMMIT() asm volatile("cp.async.commit_group;" ::: "memory")
#define CP_WAIT1()  asm volatile("cp.async.wait_group 1;" ::: "memory")

#define LDSM_X4(r, addr) \
    asm volatile("ldmatrix.sync.aligned.m8n8.x4.shared.b16 {%0,%1,%2,%3}, [%4];" \
        : "=r"((r)[0]), "=r"((r)[1]), "=r"((r)[2]), "=r"((r)[3]) : "r"(addr))

#define MMA_FP16(d, a, b) \
    asm volatile("mma.sync.aligned.m16n8k16.row.col.f32.f16.f16.f32 " \
        "{%0,%1,%2,%3}, {%4,%5,%6,%7}, {%8,%9}, {%0,%1,%2,%3};" \
        : "+f"((d)[0]), "+f"((d)[1]), "+f"((d)[2]), "+f"((d)[3]) \
        : "r"((a)[0]), "r"((a)[1]), "r"((a)[2]), "r"((a)[3]), \
          "r"((b)[0]), "r"((b)[1]))

__device__ __forceinline__ uint32_t pk(__half a, __half b) {
    return (uint32_t)__half_as_ushort(a) | ((uint32_t)__half_as_ushort(b) << 16);
}

// ---------------- router (+ g_tok init fused): one warp per token -----------
__global__ void router_kernel(const float* __restrict__ x,
                              const float* __restrict__ Wr,
                              const float* __restrict__ br) {
    int gid = blockIdx.x * blockDim.x + threadIdx.x;
    if (gid < NEXP * CAP) g_tok[gid] = -1;
    int gwarp = gid >> 5;
    int lane  = threadIdx.x & 31;
    if (gwarp >= N_TOK) return;
    const float* xr = x + (size_t)gwarp * DIM;
    float acc[NEXP];
#pragma unroll
    for (int e = 0; e < NEXP; e++) acc[e] = 0.f;
    for (int d = lane; d < DIM; d += 32) {
        float xv = xr[d];
        const float* w = Wr + d * NEXP;
#pragma unroll
        for (int e = 0; e < NEXP; e++) acc[e] += xv * w[e];
    }
#pragma unroll
    for (int o = 16; o > 0; o >>= 1)
#pragma unroll
        for (int e = 0; e < NEXP; e++)
            acc[e] += __shfl_xor_sync(0xffffffffu, acc[e], o);
    if (lane == 0) {
        float m = -1e30f; int ai = 0;
#pragma unroll
        for (int e = 0; e < NEXP; e++) {
            acc[e] += br[e];
            if (acc[e] > m) { m = acc[e]; ai = e; }   // strict > keeps first
        }
        float s = 0.f;
#pragma unroll
        for (int e = 0; e < NEXP; e++) s += expf(acc[e] - m);
        g_idx[gwarp]  = ai;
        g_gate[gwarp] = 1.f / s;
    }
}

// ---------------- order-preserving scan: 8 tokens/thread, 3-level shfl ------
__global__ void scan_kernel() {
    __shared__ unsigned long long w0s[32], w1s[32];
    int tid = threadIdx.x;          // 1024 threads
    int lane = tid & 31;
    int e8[8];
    int4 va = reinterpret_cast<const int4*>(g_idx)[tid * 2];
    int4 vb = reinterpret_cast<const int4*>(g_idx)[tid * 2 + 1];
    e8[0] = va.x; e8[1] = va.y; e8[2] = va.z; e8[3] = va.w;
    e8[4] = vb.x; e8[5] = vb.y; e8[6] = vb.z; e8[7] = vb.w;
    unsigned long long c0 = 0ull, c1 = 0ull;
#pragma unroll
    for (int i = 0; i < 8; i++) {
        int e = e8[i];
        if (e < 4) c0 += 1ull << (16 * e);
        else       c1 += 1ull << (16 * (e - 4));
    }
    unsigned long long s0 = c0, s1 = c1;
#pragma unroll
    for (int o = 1; o < 32; o <<= 1) {
        unsigned long long t0 = __shfl_up_sync(0xffffffffu, s0, o);
        unsigned long long t1 = __shfl_up_sync(0xffffffffu, s1, o);
        if (lane >= o) { s0 += t0; s1 += t1; }
    }
    if (lane == 31) { w0s[tid >> 5] = s0; w1s[tid >> 5] = s1; }
    __syncthreads();
    if (tid < 32) {
        unsigned long long a0 = w0s[tid], a1 = w1s[tid];
#pragma unroll
        for (int o = 1; o < 32; o <<= 1) {
            unsigned long long t0 = __shfl_up_sync(0xffffffffu, a0, o);
            unsigned long long t1 = __shfl_up_sync(0xffffffffu, a1, o);
            if (tid >= o) { a0 += t0; a1 += t1; }
        }
        w0s[tid] = a0; w1s[tid] = a1;
    }
    __syncthreads();
    unsigned long long p0 = s0 - c0, p1 = s1 - c1;   // exclusive within warp
    if (tid >= 32) { p0 += w0s[(tid >> 5) - 1]; p1 += w1s[(tid >> 5) - 1]; }
#pragma unroll
    for (int i = 0; i < 8; i++) {
        int n = tid * 8 + i, e = e8[i];
        int pos;
        if (e < 4) { p0 += 1ull << (16 * e);       pos = (int)((p0 >> (16 * e)) & 0xFFFFull); }
        else       { p1 += 1ull << (16 * (e - 4)); pos = (int)((p1 >> (16 * (e - 4))) & 0xFFFFull); }
        if (pos < CAP) {
            g_comb[n] = e * CAP + pos;       // 1-based pos, slot 0 unused
            g_tok[e * CAP + pos] = n;
        } else {
            g_comb[n] = -1;
        }
    }
}

// -------- dispatch scatter (gate*x -> fp16) + dropped-token zeroing ----------
__global__ void dispatch_kernel(const float* __restrict__ x,
                                float* __restrict__ out) {
    int b = blockIdx.x;
    int t = threadIdx.x;  // 256 threads x 4 elements
    if (b < NEXP * CAP) {
        int n = g_tok[b];
        uint2* dh = reinterpret_cast<uint2*>(g_Ah + (size_t)b * DIM) + t;
        if (n < 0) {
            *dh = make_uint2(0u, 0u);
        } else {
            float g = g_gate[n];
            float4 v = reinterpret_cast<const float4*>(x + (size_t)n * DIM)[t];
            *dh = make_uint2(pk(__float2half_rn(v.x * g), __float2half_rn(v.y * g)),
                             pk(__float2half_rn(v.z * g), __float2half_rn(v.w * g)));
        }
    } else {
        int n = b - NEXP * CAP;
        if (g_comb[n] < 0)
            reinterpret_cast<float4*>(out + (size_t)n * DIM)[t] =
                make_float4(0.f, 0.f, 0.f, 0.f);
    }
}

// ---------------- weight transpose fp32[k][n] -> fp16[n][k], 64x64 tiles -----
__global__ void __launch_bounds__(256) wt_kernel(const float* __restrict__ W,
                                                 __half* __restrict__ Bh) {
    __shared__ float ts[64][65];
    int e = blockIdx.z;
    int k0 = blockIdx.y * 64, n0 = blockIdx.x * 64;
    int t = threadIdx.x;
    const float* Wb = W + (size_t)e * DIM * DIM;
    int lr = t >> 4, lc = (t & 15) * 4;
#pragma unroll
    for (int i = 0; i < 4; i++) {
        int kr = lr + i * 16;
        float4 v = *reinterpret_cast<const float4*>(Wb + (size_t)(k0 + kr) * DIM + n0 + lc);
        ts[kr][lc + 0] = v.x; ts[kr][lc + 1] = v.y;
        ts[kr][lc + 2] = v.z; ts[kr][lc + 3] = v.w;
    }
    __syncthreads();
    int r  = t >> 2;             // n within tile
    int kk = (t & 3) * 16;       // k start
    uint32_t w[8];
#pragma unroll
    for (int q = 0; q < 8; q++)
        w[q] = pk(__float2half_rn(ts[kk + 2 * q][r]), __float2half_rn(ts[kk + 2 * q + 1][r]));
    size_t o = (size_t)e * DIM * DIM + (size_t)(n0 + r) * DIM + k0 + kk;
    *reinterpret_cast<uint4*>(Bh + o)     = make_uint4(w[0], w[1], w[2], w[3]);
    *reinterpret_cast<uint4*>(Bh + o + 8) = make_uint4(w[4], w[5], w[6], w[7]);
}

// ---------------- fp16 GEMM via mma.sync (single plane, BK=64) ---------------
// 128x128 CTA tile, BK=64 (128B rows, SW128), 3 stages x 32KB = 98KB, 2 CTA/SM.
#define STAGES  3
#define TILEB   16384             // 128 rows x 128B
#define NPLANES 2
#define STAGEB  (NPLANES * TILEB)
#define NCHUNK  16                // K=1024 / BK=64
#define GEMM_SMEM (2048 + STAGES * STAGEB)

// SW128 swizzle for 128B rows: seg(0..7) ^= row&7
#define SWZ128(row, seg) ((row) * 128 + (((seg) ^ ((row) & 7)) << 4))

template <bool SPLIT_RELU>
__global__ void __launch_bounds__(256, 2) gemm_mma(
    const __half* __restrict__ Ah, const __half* __restrict__ Bh,
    const float* __restrict__ bias,
    __half* __restrict__ outH, float* __restrict__ outF) {
    extern __shared__ char smem[];
    uint32_t raw = smem_u32(smem);
    uint32_t tiles = (raw + 512 + 1023) & ~1023u;
    float* sb = reinterpret_cast<float*>(smem + (tiles - 512 - raw)); // 128 floats

    const int tid = threadIdx.x;
    const int lane = tid & 31, wid = tid >> 5;
    const int bx = blockIdx.x, by = blockIdx.y, ex = blockIdx.z;

    const size_t rowA0 = (size_t)ex * 1024 + (size_t)by * 128;
    const size_t rowB0 = (size_t)ex * 1024 + (size_t)bx * 128;
    const char* pA[2] = {
        (const char*)(Ah + rowA0 * DIM), (const char*)(Bh + rowB0 * DIM)};

    if (tid < 128) sb[tid] = bias[ex * DIM + bx * 128 + tid];

    auto load_chunk = [&](int c, int s) {
        uint32_t st = tiles + s * STAGEB;
        int kb = c * 128;  // 64 fp16 = 128B per row-chunk
#pragma unroll
        for (int i = 0; i < 8; i++) {
            int g = tid + i * 256;        // 0..2047
            int tile = g >> 10;
            int j = g & 1023;
            int row = j >> 3, seg = j & 7;
            uint32_t dst = st + tile * TILEB + SWZ128(row, seg);
            const char* src = pA[tile] + (size_t)row * (DIM * 2) + kb + seg * 16;
            CP_ASYNC16(dst, src);
        }
    };

    load_chunk(0, 0); CP_COMMIT();
    load_chunk(1, 1); CP_COMMIT();

    float acc[4][4][4];
#pragma unroll
    for (int i = 0; i < 4; i++)
#pragma unroll
        for (int j = 0; j < 4; j++)
#pragma unroll
            for (int q = 0; q < 4; q++) acc[i][j][q] = 0.f;

    const int m_off = (wid & 1) * 64;    // warp tile 64x32; warps 2x4
    const int n_off = (wid >> 1) * 32;
    const int grp = lane >> 3, loc = lane & 7;
    const int rowoff_a = (grp & 1) * 8 + loc;
    const int segoff_a = grp >> 1;
    const int rowoff_b = (grp >> 1) * 8 + loc;
    const int segoff_b = grp & 1;

    for (int c = 0; c < NCHUNK; c++) {
        int s = c % STAGES;
        CP_WAIT1();                 // chunk c resident (c+1 still in flight)
        __syncthreads();            // WAR: all warps done reading stage (c+2)%3
        if (c + 2 < NCHUNK) load_chunk(c + 2, (c + 2) % STAGES);
        CP_COMMIT();
        uint32_t st = tiles + s * STAGEB;
#pragma unroll
        for (int ks = 0; ks < 4; ks++) {
            int seg0 = ks * 2;
            uint32_t bH[4][2];
#pragma unroll
            for (int p = 0; p < 2; p++) {
                int row = n_off + p * 16 + rowoff_b;
                int seg = seg0 + segoff_b;
                uint32_t bd = st + TILEB + SWZ128(row, seg);
                uint32_t r[4];
                LDSM_X4(r, bd);
                bH[2 * p][0] = r[0]; bH[2 * p][1] = r[1];
                bH[2 * p + 1][0] = r[2]; bH[2 * p + 1][1] = r[3];
            }
#pragma unroll
            for (int mt = 0; mt < 4; mt++) {
                int row = m_off + mt * 16 + rowoff_a;
                int seg = seg0 + segoff_a;
                uint32_t ad = st + SWZ128(row, seg);
                uint32_t aH[4];
                LDSM_X4(aH, ad);
#pragma unroll
                for (int nt = 0; nt < 4; nt++)
                    MMA_FP16(acc[mt][nt], aH, bH[nt]);
            }
        }
    }

    // ---- epilogue ----
    const int colb = bx * 128;
#pragma unroll
    for (int mt = 0; mt < 4; mt++) {
        size_t slot0 = rowA0 + m_off + mt * 16 + (lane >> 2);
        size_t slot1 = slot0 + 8;
        int tok0 = 0, tok1 = 0;
        float gt0 = 0.f, gt1 = 0.f;
        if (!SPLIT_RELU) {
            tok0 = g_tok[slot0];
            tok1 = g_tok[slot1];
            gt0 = (tok0 >= 0) ? g_gate[tok0] : 0.f;
            gt1 = (tok1 >= 0) ? g_gate[tok1] : 0.f;
        }
#pragma unroll
        for (int nt = 0; nt < 4; nt++) {
            int cl = n_off + nt * 8 + 2 * (lane & 3);
            float b0 = sb[cl], b1 = sb[cl + 1];
            float v00 = acc[mt][nt][0] + b0, v01 = acc[mt][nt][1] + b1;
            float v10 = acc[mt][nt][2] + b0, v11 = acc[mt][nt][3] + b1;
            if (SPLIT_RELU) {
                v00 = fmaxf(v00, 0.f); v01 = fmaxf(v01, 0.f);
                v10 = fmaxf(v10, 0.f); v11 = fmaxf(v11, 0.f);
                *reinterpret_cast<uint32_t*>(outH + slot0 * DIM + colb + cl) =
                    pk(__float2half_rn(v00), __float2half_rn(v01));
                *reinterpret_cast<uint32_t*>(outH + slot1 * DIM + colb + cl) =
                    pk(__float2half_rn(v10), __float2half_rn(v11));
            } else {
                // fused combine: out[token] = gate * (eo + bias)
                if (tok0 >= 0)
                    *reinterpret_cast<float2*>(outF + (size_t)tok0 * DIM + colb + cl) =
                        make_float2(gt0 * v00, gt0 * v01);
                if (tok1 >= 0)
                    *reinterpret_cast<float2*>(outF + (size_t)tok1 * DIM + colb + cl) =
                        make_float2(gt1 * v10, gt1 * v11);
            }
        }
    }
}

// ---------------- launch -------------------------------------------------------
extern "C" void kernel_launch(void* const* d_in, const int* in_sizes, int n_in,
                              void* d_out, int out_size) {
    const float* x  = (const float*)d_in[0];
    const float* Wr = (const float*)d_in[1];
    const float* br = (const float*)d_in[2];
    const float* W1 = (const float*)d_in[3];
    const float* b1 = (const float*)d_in[4];
    const float* W2 = (const float*)d_in[5];
    const float* b2 = (const float*)d_in[6];
    float* out = (float*)d_out;

    void *pAh, *pHh, *pB1h, *pB2h;
    cudaGetSymbolAddress(&pAh, g_Ah);
    cudaGetSymbolAddress(&pHh, g_Hh);
    cudaGetSymbolAddress(&pB1h, g_B1h);
    cudaGetSymbolAddress(&pB2h, g_B2h);

    cudaFuncSetAttribute(gemm_mma<true>,  cudaFuncAttributeMaxDynamicSharedMemorySize, GEMM_SMEM);
    cudaFuncSetAttribute(gemm_mma<false>, cudaFuncAttributeMaxDynamicSharedMemorySize, GEMM_SMEM);

    // side stream + events (created once; host resources only, device work is
    // identical on every call -> deterministic & graph-capturable fork/join)
    static cudaStream_t s_side = nullptr;
    static cudaEvent_t  ev_root = nullptr, ev_wt = nullptr;
    if (s_side == nullptr) {
        cudaStreamCreateWithFlags(&s_side, cudaStreamNonBlocking);
        cudaEventCreateWithFlags(&ev_root, cudaEventDisableTiming);
        cudaEventCreateWithFlags(&ev_wt,   cudaEventDisableTiming);
    }

    // fork: weight conversion runs concurrently with router/scan/dispatch
    cudaEventRecord(ev_root, 0);
    cudaStreamWaitEvent(s_side, ev_root, 0);
    dim3 wtg(16, 16, NEXP);
    wt_kernel<<<wtg, 256, 0, s_side>>>(W1, (__half*)pB1h);
    wt_kernel<<<wtg, 256, 0, s_side>>>(W2, (__half*)pB2h);
    cudaEventRecord(ev_wt, s_side);

    // main chain
    router_kernel<<<N_TOK * 32 / 256, 256>>>(x, Wr, br);
    scan_kernel<<<1, 1024>>>();
    dispatch_kernel<<<2 * NEXP * CAP, 256>>>(x, out);

    // join: GEMMs need converted weights
    cudaStreamWaitEvent(0, ev_wt, 0);

    dim3 gg(8, 8, NEXP);
    gemm_mma<true><<<gg, 256, GEMM_SMEM>>>(
        (const __half*)pAh, (const __half*)pB1h, b1, (__half*)pHh, nullptr);
    gemm_mma<false><<<gg, 256, GEMM_SMEM>>>(
        (const __half*)pHh, (const __half*)pB2h, b2, nullptr, out);
}

// round 11
// speedup vs baseline: 3.8183x; 1.0069x over previous
#include <cuda_runtime.h>
#include <cuda_fp16.h>
#include <cstdint>

#define N_TOK 8192
#define DIM   1024
#define NEXP  8
#define CAP   1024
#define SCAN_BLOCKS 8

// ---------------- scratch (device globals; no allocation allowed) ----------
__device__ __half g_Ah[(size_t)N_TOK * DIM];   // expert_in fp16
__device__ __half g_Hh[(size_t)N_TOK * DIM];   // hidden fp16
__device__ __half g_B1h[(size_t)N_TOK * DIM];  // W1^T fp16 [e][n][k]
__device__ __half g_B2h[(size_t)N_TOK * DIM];  // W2^T fp16
__device__ int   g_idx[N_TOK];
__device__ float g_gate[N_TOK];
__device__ int   g_comb[N_TOK];
__device__ int   g_tok[NEXP * CAP];
__device__ unsigned long long g_agg0[SCAN_BLOCKS], g_agg1[SCAN_BLOCKS];
__device__ int   g_flag[SCAN_BLOCKS];

// ---------------- PTX helpers (sm_80-level only) -----------------------------
__device__ __forceinline__ uint32_t smem_u32(const void* p) {
    uint32_t a;
    asm("{ .reg .u64 t; cvta.to.shared.u64 t, %1; cvt.u32.u64 %0, t; }"
        : "=r"(a) : "l"(p));
    return a;
}

#define CP_ASYNC16(dst, src) \
    asm volatile("cp.async.cg.shared.global [%0], [%1], 16;" :: "r"(dst), "l"(src) : "memory")
#define CP_COMMIT() asm volatile("cp.async.commit_group;" ::: "memory")
#define CP_WAIT1()  asm volatile("cp.async.wait_group 1;" ::: "memory")

#define LDSM_X4(r, addr) \
    asm volatile("ldmatrix.sync.aligned.m8n8.x4.shared.b16 {%0,%1,%2,%3}, [%4];" \
        : "=r"((r)[0]), "=r"((r)[1]), "=r"((r)[2]), "=r"((r)[3]) : "r"(addr))

#define MMA_FP16(d, a, b) \
    asm volatile("mma.sync.aligned.m16n8k16.row.col.f32.f16.f16.f32 " \
        "{%0,%1,%2,%3}, {%4,%5,%6,%7}, {%8,%9}, {%0,%1,%2,%3};" \
        : "+f"((d)[0]), "+f"((d)[1]), "+f"((d)[2]), "+f"((d)[3]) \
        : "r"((a)[0]), "r"((a)[1]), "r"((a)[2]), "r"((a)[3]), \
          "r"((b)[0]), "r"((b)[1]))

__device__ __forceinline__ uint32_t pk(__half a, __half b) {
    return (uint32_t)__half_as_ushort(a) | ((uint32_t)__half_as_ushort(b) << 16);
}

// ---------------- router (+ g_tok & scan-flag init fused) --------------------
__global__ void router_kernel(const float* __restrict__ x,
                              const float* __restrict__ Wr,
                              const float* __restrict__ br) {
    int gid = blockIdx.x * blockDim.x + threadIdx.x;
    if (gid < NEXP * CAP) g_tok[gid] = -1;
    if (gid < SCAN_BLOCKS) g_flag[gid] = 0;
    int gwarp = gid >> 5;
    int lane  = threadIdx.x & 31;
    if (gwarp >= N_TOK) return;
    const float* xr = x + (size_t)gwarp * DIM;
    float acc[NEXP];
#pragma unroll
    for (int e = 0; e < NEXP; e++) acc[e] = 0.f;
    for (int d = lane; d < DIM; d += 32) {
        float xv = xr[d];
        const float* w = Wr + d * NEXP;
#pragma unroll
        for (int e = 0; e < NEXP; e++) acc[e] += xv * w[e];
    }
#pragma unroll
    for (int o = 16; o > 0; o >>= 1)
#pragma unroll
        for (int e = 0; e < NEXP; e++)
            acc[e] += __shfl_xor_sync(0xffffffffu, acc[e], o);
    if (lane == 0) {
        float m = -1e30f; int ai = 0;
#pragma unroll
        for (int e = 0; e < NEXP; e++) {
            acc[e] += br[e];
            if (acc[e] > m) { m = acc[e]; ai = e; }   // strict > keeps first
        }
        float s = 0.f;
#pragma unroll
        for (int e = 0; e < NEXP; e++) s += expf(acc[e] - m);
        g_idx[gwarp]  = ai;
        g_gate[gwarp] = 1.f / s;
    }
}

// -------- order-preserving scan: 8 blocks, chained cross-block prefix --------
// All 8 blocks are co-resident (148 SMs), so the flag chain cannot deadlock.
// Flags are reset by router_kernel each call -> deterministic on graph replay.
__global__ void __launch_bounds__(1024) scan_kernel() {
    __shared__ unsigned long long w0s[32], w1s[32];
    __shared__ unsigned long long prev0s, prev1s;
    int b = blockIdx.x;
    int tid = threadIdx.x, lane = tid & 31, wp = tid >> 5;
    int n = b * 1024 + tid;
    int e = g_idx[n];
    unsigned long long c0 = (e < 4) ? (1ull << (16 * e)) : 0ull;
    unsigned long long c1 = (e < 4) ? 0ull : (1ull << (16 * (e - 4)));
    unsigned long long s0 = c0, s1 = c1;
#pragma unroll
    for (int o = 1; o < 32; o <<= 1) {
        unsigned long long t0 = __shfl_up_sync(0xffffffffu, s0, o);
        unsigned long long t1 = __shfl_up_sync(0xffffffffu, s1, o);
        if (lane >= o) { s0 += t0; s1 += t1; }
    }
    if (lane == 31) { w0s[wp] = s0; w1s[wp] = s1; }
    __syncthreads();
    if (tid < 32) {
        unsigned long long a0 = w0s[tid], a1 = w1s[tid];
#pragma unroll
        for (int o = 1; o < 32; o <<= 1) {
            unsigned long long t0 = __shfl_up_sync(0xffffffffu, a0, o);
            unsigned long long t1 = __shfl_up_sync(0xffffffffu, a1, o);
            if (tid >= o) { a0 += t0; a1 += t1; }
        }
        w0s[tid] = a0; w1s[tid] = a1;
    }
    __syncthreads();
    if (tid == 0) {
        unsigned long long t0 = w0s[31], t1 = w1s[31];  // block totals
        unsigned long long p0 = 0ull, p1 = 0ull;
        if (b > 0) {
            while (atomicAdd(&g_flag[b - 1], 0) == 0) { }
            __threadfence();
            p0 = g_agg0[b - 1]; p1 = g_agg1[b - 1];
        }
        prev0s = p0; prev1s = p1;
        g_agg0[b] = p0 + t0; g_agg1[b] = p1 + t1;
        __threadfence();
        atomicExch(&g_flag[b], 1);
    }
    __syncthreads();
    // global inclusive = cross-block prefix + warp prefix + within-warp inclusive
    unsigned long long i0 = prev0s + (wp ? w0s[wp - 1] : 0ull) + s0;
    unsigned long long i1 = prev1s + (wp ? w1s[wp - 1] : 0ull) + s1;
    int pos = (e < 4) ? (int)((i0 >> (16 * e)) & 0xFFFFull)
                      : (int)((i1 >> (16 * (e - 4))) & 0xFFFFull);
    if (pos < CAP) {
        g_comb[n] = e * CAP + pos;           // 1-based pos, slot 0 unused
        g_tok[e * CAP + pos] = n;
    } else {
        g_comb[n] = -1;
    }
}

// -------- dispatch scatter (gate*x -> fp16) + dropped-token zeroing ----------
__global__ void dispatch_kernel(const float* __restrict__ x,
                                float* __restrict__ out) {
    int b = blockIdx.x;
    int t = threadIdx.x;  // 256 threads x 4 elements
    if (b < NEXP * CAP) {
        int n = g_tok[b];
        uint2* dh = reinterpret_cast<uint2*>(g_Ah + (size_t)b * DIM) + t;
        if (n < 0) {
            *dh = make_uint2(0u, 0u);
        } else {
            float g = g_gate[n];
            float4 v = reinterpret_cast<const float4*>(x + (size_t)n * DIM)[t];
            *dh = make_uint2(pk(__float2half_rn(v.x * g), __float2half_rn(v.y * g)),
                             pk(__float2half_rn(v.z * g), __float2half_rn(v.w * g)));
        }
    } else {
        int n = b - NEXP * CAP;
        if (g_comb[n] < 0)
            reinterpret_cast<float4*>(out + (size_t)n * DIM)[t] =
                make_float4(0.f, 0.f, 0.f, 0.f);
    }
}

// ---------------- weight transpose fp32[k][n] -> fp16[n][k], 64x64 tiles -----
__global__ void __launch_bounds__(256) wt_kernel(const float* __restrict__ W,
                                                 __half* __restrict__ Bh) {
    __shared__ float ts[64][65];
    int e = blockIdx.z;
    int k0 = blockIdx.y * 64, n0 = blockIdx.x * 64;
    int t = threadIdx.x;
    const float* Wb = W + (size_t)e * DIM * DIM;
    int lr = t >> 4, lc = (t & 15) * 4;
#pragma unroll
    for (int i = 0; i < 4; i++) {
        int kr = lr + i * 16;
        float4 v = *reinterpret_cast<const float4*>(Wb + (size_t)(k0 + kr) * DIM + n0 + lc);
        ts[kr][lc + 0] = v.x; ts[kr][lc + 1] = v.y;
        ts[kr][lc + 2] = v.z; ts[kr][lc + 3] = v.w;
    }
    __syncthreads();
    int r  = t >> 2;             // n within tile
    int kk = (t & 3) * 16;       // k start
    uint32_t w[8];
#pragma unroll
    for (int q = 0; q < 8; q++)
        w[q] = pk(__float2half_rn(ts[kk + 2 * q][r]), __float2half_rn(ts[kk + 2 * q + 1][r]));
    size_t o = (size_t)e * DIM * DIM + (size_t)(n0 + r) * DIM + k0 + kk;
    *reinterpret_cast<uint4*>(Bh + o)     = make_uint4(w[0], w[1], w[2], w[3]);
    *reinterpret_cast<uint4*>(Bh + o + 8) = make_uint4(w[4], w[5], w[6], w[7]);
}

// ---------------- fp16 GEMM via mma.sync (single plane, BK=64) ---------------
// 128x128 CTA tile, BK=64 (128B rows, SW128), 3 stages x 32KB = 98KB, 2 CTA/SM.
#define STAGES  3
#define TILEB   16384             // 128 rows x 128B
#define NPLANES 2
#define STAGEB  (NPLANES * TILEB)
#define NCHUNK  16                // K=1024 / BK=64
#define GEMM_SMEM (2048 + STAGES * STAGEB)

// SW128 swizzle for 128B rows: seg(0..7) ^= row&7
#define SWZ128(row, seg) ((row) * 128 + (((seg) ^ ((row) & 7)) << 4))

template <bool SPLIT_RELU>
__global__ void __launch_bounds__(256, 2) gemm_mma(
    const __half* __restrict__ Ah, const __half* __restrict__ Bh,
    const float* __restrict__ bias,
    __half* __restrict__ outH, float* __restrict__ outF) {
    extern __shared__ char smem[];
    uint32_t raw = smem_u32(smem);
    uint32_t tiles = (raw + 512 + 1023) & ~1023u;
    float* sb = reinterpret_cast<float*>(smem + (tiles - 512 - raw)); // 128 floats

    const int tid = threadIdx.x;
    const int lane = tid & 31, wid = tid >> 5;
    const int bx = blockIdx.x, by = blockIdx.y, ex = blockIdx.z;

    const size_t rowA0 = (size_t)ex * 1024 + (size_t)by * 128;
    const size_t rowB0 = (size_t)ex * 1024 + (size_t)bx * 128;
    const char* pA[2] = {
        (const char*)(Ah + rowA0 * DIM), (const char*)(Bh + rowB0 * DIM)};

    if (tid < 128) sb[tid] = bias[ex * DIM + bx * 128 + tid];

    auto load_chunk = [&](int c, int s) {
        uint32_t st = tiles + s * STAGEB;
        int kb = c * 128;  // 64 fp16 = 128B per row-chunk
#pragma unroll
        for (int i = 0; i < 8; i++) {
            int g = tid + i * 256;        // 0..2047
            int tile = g >> 10;
            int j = g & 1023;
            int row = j >> 3, seg = j & 7;
            uint32_t dst = st + tile * TILEB + SWZ128(row, seg);
            const char* src = pA[tile] + (size_t)row * (DIM * 2) + kb + seg * 16;
            CP_ASYNC16(dst, src);
        }
    };

    load_chunk(0, 0); CP_COMMIT();
    load_chunk(1, 1); CP_COMMIT();

    float acc[4][4][4];
#pragma unroll
    for (int i = 0; i < 4; i++)
#pragma unroll
        for (int j = 0; j < 4; j++)
#pragma unroll
            for (int q = 0; q < 4; q++) acc[i][j][q] = 0.f;

    const int m_off = (wid & 1) * 64;    // warp tile 64x32; warps 2x4
    const int n_off = (wid >> 1) * 32;
    const int grp = lane >> 3, loc = lane & 7;
    const int rowoff_a = (grp & 1) * 8 + loc;
    const int segoff_a = grp >> 1;
    const int rowoff_b = (grp >> 1) * 8 + loc;
    const int segoff_b = grp & 1;

    for (int c = 0; c < NCHUNK; c++) {
        int s = c % STAGES;
        CP_WAIT1();                 // chunk c resident (c+1 still in flight)
        __syncthreads();            // WAR: all warps done reading stage (c+2)%3
        if (c + 2 < NCHUNK) load_chunk(c + 2, (c + 2) % STAGES);
        CP_COMMIT();
        uint32_t st = tiles + s * STAGEB;
#pragma unroll
        for (int ks = 0; ks < 4; ks++) {
            int seg0 = ks * 2;
            uint32_t bH[4][2];
#pragma unroll
            for (int p = 0; p < 2; p++) {
                int row = n_off + p * 16 + rowoff_b;
                int seg = seg0 + segoff_b;
                uint32_t bd = st + TILEB + SWZ128(row, seg);
                uint32_t r[4];
                LDSM_X4(r, bd);
                bH[2 * p][0] = r[0]; bH[2 * p][1] = r[1];
                bH[2 * p + 1][0] = r[2]; bH[2 * p + 1][1] = r[3];
            }
#pragma unroll
            for (int mt = 0; mt < 4; mt++) {
                int row = m_off + mt * 16 + rowoff_a;
                int seg = seg0 + segoff_a;
                uint32_t ad = st + SWZ128(row, seg);
                uint32_t aH[4];
                LDSM_X4(aH, ad);
#pragma unroll
                for (int nt = 0; nt < 4; nt++)
                    MMA_FP16(acc[mt][nt], aH, bH[nt]);
            }
        }
    }

    // ---- epilogue ----
    const int colb = bx * 128;
#pragma unroll
    for (int mt = 0; mt < 4; mt++) {
        size_t slot0 = rowA0 + m_off + mt * 16 + (lane >> 2);
        size_t slot1 = slot0 + 8;
        int tok0 = 0, tok1 = 0;
        float gt0 = 0.f, gt1 = 0.f;
        if (!SPLIT_RELU) {
            tok0 = g_tok[slot0];
            tok1 = g_tok[slot1];
            gt0 = (tok0 >= 0) ? g_gate[tok0] : 0.f;
            gt1 = (tok1 >= 0) ? g_gate[tok1] : 0.f;
        }
#pragma unroll
        for (int nt = 0; nt < 4; nt++) {
            int cl = n_off + nt * 8 + 2 * (lane & 3);
            float b0 = sb[cl], b1 = sb[cl + 1];
            float v00 = acc[mt][nt][0] + b0, v01 = acc[mt][nt][1] + b1;
            float v10 = acc[mt][nt][2] + b0, v11 = acc[mt][nt][3] + b1;
            if (SPLIT_RELU) {
                v00 = fmaxf(v00, 0.f); v01 = fmaxf(v01, 0.f);
                v10 = fmaxf(v10, 0.f); v11 = fmaxf(v11, 0.f);
                *reinterpret_cast<uint32_t*>(outH + slot0 * DIM + colb + cl) =
                    pk(__float2half_rn(v00), __float2half_rn(v01));
                *reinterpret_cast<uint32_t*>(outH + slot1 * DIM + colb + cl) =
                    pk(__float2half_rn(v10), __float2half_rn(v11));
            } else {
                // fused combine: out[token] = gate * (eo + bias)
                if (tok0 >= 0)
                    *reinterpret_cast<float2*>(outF + (size_t)tok0 * DIM + colb + cl) =
                        make_float2(gt0 * v00, gt0 * v01);
                if (tok1 >= 0)
                    *reinterpret_cast<float2*>(outF + (size_t)tok1 * DIM + colb + cl) =
                        make_float2(gt1 * v10, gt1 * v11);
            }
        }
    }
}

// ---------------- launch -------------------------------------------------------
extern "C" void kernel_launch(void* const* d_in, const int* in_sizes, int n_in,
                              void* d_out, int out_size) {
    const float* x  = (const float*)d_in[0];
    const float* Wr = (const float*)d_in[1];
    const float* br = (const float*)d_in[2];
    const float* W1 = (const float*)d_in[3];
    const float* b1 = (const float*)d_in[4];
    const float* W2 = (const float*)d_in[5];
    const float* b2 = (const float*)d_in[6];
    float* out = (float*)d_out;

    void *pAh, *pHh, *pB1h, *pB2h;
    cudaGetSymbolAddress(&pAh, g_Ah);
    cudaGetSymbolAddress(&pHh, g_Hh);
    cudaGetSymbolAddress(&pB1h, g_B1h);
    cudaGetSymbolAddress(&pB2h, g_B2h);

    cudaFuncSetAttribute(gemm_mma<true>,  cudaFuncAttributeMaxDynamicSharedMemorySize, GEMM_SMEM);
    cudaFuncSetAttribute(gemm_mma<false>, cudaFuncAttributeMaxDynamicSharedMemorySize, GEMM_SMEM);

    // single side stream + 2 events (exact round-8 layout: verified delta=0)
    static cudaStream_t s_side = nullptr;
    static cudaEvent_t  ev_root = nullptr, ev_wt = nullptr;
    if (s_side == nullptr) {
        cudaStreamCreateWithFlags(&s_side, cudaStreamNonBlocking);
        cudaEventCreateWithFlags(&ev_root, cudaEventDisableTiming);
        cudaEventCreateWithFlags(&ev_wt,   cudaEventDisableTiming);
    }

    // fork: weight conversion runs concurrently with router/scan/dispatch
    cudaEventRecord(ev_root, 0);
    cudaStreamWaitEvent(s_side, ev_root, 0);
    dim3 wtg(16, 16, NEXP);
    wt_kernel<<<wtg, 256, 0, s_side>>>(W1, (__half*)pB1h);
    wt_kernel<<<wtg, 256, 0, s_side>>>(W2, (__half*)pB2h);
    cudaEventRecord(ev_wt, s_side);

    // main chain
    router_kernel<<<N_TOK * 32 / 256, 256>>>(x, Wr, br);
    scan_kernel<<<SCAN_BLOCKS, 1024>>>();
    dispatch_kernel<<<2 * NEXP * CAP, 256>>>(x, out);

    // join: GEMMs need converted weights
    cudaStreamWaitEvent(0, ev_wt, 0);

    dim3 gg(8, 8, NEXP);
    gemm_mma<true><<<gg, 256, GEMM_SMEM>>>(
        (const __half*)pAh, (const __half*)pB1h, b1, (__half*)pHh, nullptr);
    gemm_mma<false><<<gg, 256, GEMM_SMEM>>>(
        (const __half*)pHh, (const __half*)pB2h, b2, nullptr, out);
}

// round 12
// speedup vs baseline: 4.0044x; 1.0487x over previous
#include <cuda_runtime.h>
#include <cuda_fp16.h>
#include <cstdint>

#define N_TOK 8192
#define DIM   1024
#define NEXP  8
#define CAP   1024
#define SCAN_BLOCKS 8
#define TILES_PER_EXPERT 64   // 8x8 tiles of 128x128
#define G1_BLOCKS (NEXP * TILES_PER_EXPERT)

// ---------------- scratch (device globals; no allocation allowed) ----------
__device__ __half g_Ah[(size_t)N_TOK * DIM];   // expert_in fp16
__device__ __half g_Hh[(size_t)N_TOK * DIM];   // hidden fp16
__device__ __half g_B1h[(size_t)N_TOK * DIM];  // W1^T fp16 [e][n][k]
__device__ __half g_B2h[(size_t)N_TOK * DIM];  // W2^T fp16
__device__ int   g_idx[N_TOK];
__device__ float g_gate[N_TOK];
__device__ int   g_comb[N_TOK];
__device__ int   g_tok[NEXP * CAP];
__device__ unsigned long long g_agg0[SCAN_BLOCKS], g_agg1[SCAN_BLOCKS];
__device__ int   g_flag[SCAN_BLOCKS];
__device__ int   g_done[NEXP];                 // GEMM1 tile completion per expert

// ---------------- PTX helpers (sm_80-level only) -----------------------------
__device__ __forceinline__ uint32_t smem_u32(const void* p) {
    uint32_t a;
    asm("{ .reg .u64 t; cvta.to.shared.u64 t, %1; cvt.u32.u64 %0, t; }"
        : "=r"(a) : "l"(p));
    return a;
}

#define CP_ASYNC16(dst, src) \
    asm volatile("cp.async.cg.shared.global [%0], [%1], 16;" :: "r"(dst), "l"(src) : "memory")
#define CP_COMMIT() asm volatile("cp.async.commit_group;" ::: "memory")
#define CP_WAIT1()  asm volatile("cp.async.wait_group 1;" ::: "memory")

#define LDSM_X4(r, addr) \
    asm volatile("ldmatrix.sync.aligned.m8n8.x4.shared.b16 {%0,%1,%2,%3}, [%4];" \
        : "=r"((r)[0]), "=r"((r)[1]), "=r"((r)[2]), "=r"((r)[3]) : "r"(addr))

#define MMA_FP16(d, a, b) \
    asm volatile("mma.sync.aligned.m16n8k16.row.col.f32.f16.f16.f32 " \
        "{%0,%1,%2,%3}, {%4,%5,%6,%7}, {%8,%9}, {%0,%1,%2,%3};" \
        : "+f"((d)[0]), "+f"((d)[1]), "+f"((d)[2]), "+f"((d)[3]) \
        : "r"((a)[0]), "r"((a)[1]), "r"((a)[2]), "r"((a)[3]), \
          "r"((b)[0]), "r"((b)[1]))

__device__ __forceinline__ uint32_t pk(__half a, __half b) {
    return (uint32_t)__half_as_ushort(a) | ((uint32_t)__half_as_ushort(b) << 16);
}

// ---------------- router (+ g_tok / scan-flag / g_done init fused) -----------
__global__ void router_kernel(const float* __restrict__ x,
                              const float* __restrict__ Wr,
                              const float* __restrict__ br) {
    int gid = blockIdx.x * blockDim.x + threadIdx.x;
    if (gid < NEXP * CAP) g_tok[gid] = -1;
    if (gid < SCAN_BLOCKS) g_flag[gid] = 0;
    if (gid >= SCAN_BLOCKS && gid < SCAN_BLOCKS + NEXP) g_done[gid - SCAN_BLOCKS] = 0;
    int gwarp = gid >> 5;
    int lane  = threadIdx.x & 31;
    if (gwarp >= N_TOK) return;
    const float* xr = x + (size_t)gwarp * DIM;
    float acc[NEXP];
#pragma unroll
    for (int e = 0; e < NEXP; e++) acc[e] = 0.f;
    for (int d = lane; d < DIM; d += 32) {
        float xv = xr[d];
        const float* w = Wr + d * NEXP;
#pragma unroll
        for (int e = 0; e < NEXP; e++) acc[e] += xv * w[e];
    }
#pragma unroll
    for (int o = 16; o > 0; o >>= 1)
#pragma unroll
        for (int e = 0; e < NEXP; e++)
            acc[e] += __shfl_xor_sync(0xffffffffu, acc[e], o);
    if (lane == 0) {
        float m = -1e30f; int ai = 0;
#pragma unroll
        for (int e = 0; e < NEXP; e++) {
            acc[e] += br[e];
            if (acc[e] > m) { m = acc[e]; ai = e; }   // strict > keeps first
        }
        float s = 0.f;
#pragma unroll
        for (int e = 0; e < NEXP; e++) s += expf(acc[e] - m);
        g_idx[gwarp]  = ai;
        g_gate[gwarp] = 1.f / s;
    }
}

// -------- order-preserving scan: 8 blocks, chained cross-block prefix --------
__global__ void __launch_bounds__(1024) scan_kernel() {
    __shared__ unsigned long long w0s[32], w1s[32];
    __shared__ unsigned long long prev0s, prev1s;
    int b = blockIdx.x;
    int tid = threadIdx.x, lane = tid & 31, wp = tid >> 5;
    int n = b * 1024 + tid;
    int e = g_idx[n];
    unsigned long long c0 = (e < 4) ? (1ull << (16 * e)) : 0ull;
    unsigned long long c1 = (e < 4) ? 0ull : (1ull << (16 * (e - 4)));
    unsigned long long s0 = c0, s1 = c1;
#pragma unroll
    for (int o = 1; o < 32; o <<= 1) {
        unsigned long long t0 = __shfl_up_sync(0xffffffffu, s0, o);
        unsigned long long t1 = __shfl_up_sync(0xffffffffu, s1, o);
        if (lane >= o) { s0 += t0; s1 += t1; }
    }
    if (lane == 31) { w0s[wp] = s0; w1s[wp] = s1; }
    __syncthreads();
    if (tid < 32) {
        unsigned long long a0 = w0s[tid], a1 = w1s[tid];
#pragma unroll
        for (int o = 1; o < 32; o <<= 1) {
            unsigned long long t0 = __shfl_up_sync(0xffffffffu, a0, o);
            unsigned long long t1 = __shfl_up_sync(0xffffffffu, a1, o);
            if (tid >= o) { a0 += t0; a1 += t1; }
        }
        w0s[tid] = a0; w1s[tid] = a1;
    }
    __syncthreads();
    if (tid == 0) {
        unsigned long long t0 = w0s[31], t1 = w1s[31];  // block totals
        unsigned long long p0 = 0ull, p1 = 0ull;
        if (b > 0) {
            while (atomicAdd(&g_flag[b - 1], 0) == 0) { }
            __threadfence();
            p0 = g_agg0[b - 1]; p1 = g_agg1[b - 1];
        }
        prev0s = p0; prev1s = p1;
        g_agg0[b] = p0 + t0; g_agg1[b] = p1 + t1;
        __threadfence();
        atomicExch(&g_flag[b], 1);
    }
    __syncthreads();
    unsigned long long i0 = prev0s + (wp ? w0s[wp - 1] : 0ull) + s0;
    unsigned long long i1 = prev1s + (wp ? w1s[wp - 1] : 0ull) + s1;
    int pos = (e < 4) ? (int)((i0 >> (16 * e)) & 0xFFFFull)
                      : (int)((i1 >> (16 * (e - 4))) & 0xFFFFull);
    if (pos < CAP) {
        g_comb[n] = e * CAP + pos;           // 1-based pos, slot 0 unused
        g_tok[e * CAP + pos] = n;
    } else {
        g_comb[n] = -1;
    }
}

// -------- dispatch scatter (gate*x -> fp16) + dropped-token zeroing ----------
__global__ void dispatch_kernel(const float* __restrict__ x,
                                float* __restrict__ out) {
    int b = blockIdx.x;
    int t = threadIdx.x;  // 256 threads x 4 elements
    if (b < NEXP * CAP) {
        int n = g_tok[b];
        uint2* dh = reinterpret_cast<uint2*>(g_Ah + (size_t)b * DIM) + t;
        if (n < 0) {
            *dh = make_uint2(0u, 0u);
        } else {
            float g = g_gate[n];
            float4 v = reinterpret_cast<const float4*>(x + (size_t)n * DIM)[t];
            *dh = make_uint2(pk(__float2half_rn(v.x * g), __float2half_rn(v.y * g)),
                             pk(__float2half_rn(v.z * g), __float2half_rn(v.w * g)));
        }
    } else {
        int n = b - NEXP * CAP;
        if (g_comb[n] < 0)
            reinterpret_cast<float4*>(out + (size_t)n * DIM)[t] =
                make_float4(0.f, 0.f, 0.f, 0.f);
    }
}

// ---------------- weight transpose fp32[k][n] -> fp16[n][k], 64x64 tiles -----
__global__ void __launch_bounds__(256) wt_kernel(const float* __restrict__ W,
                                                 __half* __restrict__ Bh) {
    __shared__ float ts[64][65];
    int e = blockIdx.z;
    int k0 = blockIdx.y * 64, n0 = blockIdx.x * 64;
    int t = threadIdx.x;
    const float* Wb = W + (size_t)e * DIM * DIM;
    int lr = t >> 4, lc = (t & 15) * 4;
#pragma unroll
    for (int i = 0; i < 4; i++) {
        int kr = lr + i * 16;
        float4 v = *reinterpret_cast<const float4*>(Wb + (size_t)(k0 + kr) * DIM + n0 + lc);
        ts[kr][lc + 0] = v.x; ts[kr][lc + 1] = v.y;
        ts[kr][lc + 2] = v.z; ts[kr][lc + 3] = v.w;
    }
    __syncthreads();
    int r  = t >> 2;             // n within tile
    int kk = (t & 3) * 16;       // k start
    uint32_t w[8];
#pragma unroll
    for (int q = 0; q < 8; q++)
        w[q] = pk(__float2half_rn(ts[kk + 2 * q][r]), __float2half_rn(ts[kk + 2 * q + 1][r]));
    size_t o = (size_t)e * DIM * DIM + (size_t)(n0 + r) * DIM + k0 + kk;
    *reinterpret_cast<uint4*>(Bh + o)     = make_uint4(w[0], w[1], w[2], w[3]);
    *reinterpret_cast<uint4*>(Bh + o + 8) = make_uint4(w[4], w[5], w[6], w[7]);
}

// -------- fused GEMM1+GEMM2 via mma.sync, device-side per-expert sync --------
// bids [0, 512):    GEMM1 tile  h = relu(A @ W1^T + b1)   -> g_Hh, g_done[e]++
// bids [512, 1024): GEMM2 tile  out[tok] = gate*(h @ W2^T + b2), spins on g_done
// Deadlock-free: CWD dispatches ascending bid, GEMM1 blocks never spin.
#define STAGES  3
#define TILEB   16384             // 128 rows x 128B
#define NPLANES 2
#define STAGEB  (NPLANES * TILEB)
#define NCHUNK  16                // K=1024 / BK=64
#define GEMM_SMEM (2048 + STAGES * STAGEB)

// SW128 swizzle for 128B rows: seg(0..7) ^= row&7
#define SWZ128(row, seg) ((row) * 128 + (((seg) ^ ((row) & 7)) << 4))

__global__ void __launch_bounds__(256, 2) gemm_fused(
    const __half* __restrict__ B1h, const float* __restrict__ b1,
    const __half* __restrict__ B2h, const float* __restrict__ b2,
    float* __restrict__ out) {
    extern __shared__ char smem[];
    uint32_t raw = smem_u32(smem);
    uint32_t tiles = (raw + 512 + 1023) & ~1023u;
    float* sb = reinterpret_cast<float*>(smem + (tiles - 512 - raw)); // 128 floats

    const int tid = threadIdx.x;
    const int lane = tid & 31, wid = tid >> 5;
    const int bid = blockIdx.x;
    const bool phase2 = bid >= G1_BLOCKS;
    const int lb = phase2 ? bid - G1_BLOCKS : bid;
    const int ex = lb >> 6;
    const int tl = lb & 63;
    const int bx = tl & 7, by = tl >> 3;

    // GEMM2: wait for this expert's GEMM1 tiles
    if (phase2) {
        if (tid == 0)
            while (atomicAdd(&g_done[ex], 0) < TILES_PER_EXPERT) { }
        __syncthreads();
        __threadfence();
    }

    const __half* Ain  = phase2 ? g_Hh : g_Ah;
    const __half* Bin  = phase2 ? B2h  : B1h;
    const float*  bias = phase2 ? b2   : b1;

    const size_t rowA0 = (size_t)ex * 1024 + (size_t)by * 128;
    const size_t rowB0 = (size_t)ex * 1024 + (size_t)bx * 128;
    const char* pA[2] = {
        (const char*)(Ain + rowA0 * DIM), (const char*)(Bin + rowB0 * DIM)};

    if (tid < 128) sb[tid] = bias[ex * DIM + bx * 128 + tid];

    auto load_chunk = [&](int c, int s) {
        uint32_t st = tiles + s * STAGEB;
        int kb = c * 128;  // 64 fp16 = 128B per row-chunk
#pragma unroll
        for (int i = 0; i < 8; i++) {
            int g = tid + i * 256;        // 0..2047
            int tile = g >> 10;
            int j = g & 1023;
            int row = j >> 3, seg = j & 7;
            uint32_t dst = st + tile * TILEB + SWZ128(row, seg);
            const char* src = pA[tile] + (size_t)row * (DIM * 2) + kb + seg * 16;
            CP_ASYNC16(dst, src);
        }
    };

    load_chunk(0, 0); CP_COMMIT();
    load_chunk(1, 1); CP_COMMIT();

    float acc[4][4][4];
#pragma unroll
    for (int i = 0; i < 4; i++)
#pragma unroll
        for (int j = 0; j < 4; j++)
#pragma unroll
            for (int q = 0; q < 4; q++) acc[i][j][q] = 0.f;

    const int m_off = (wid & 1) * 64;    // warp tile 64x32; warps 2x4
    const int n_off = (wid >> 1) * 32;
    const int grp = lane >> 3, loc = lane & 7;
    const int rowoff_a = (grp & 1) * 8 + loc;
    const int segoff_a = grp >> 1;
    const int rowoff_b = (grp >> 1) * 8 + loc;
    const int segoff_b = grp & 1;

    for (int c = 0; c < NCHUNK; c++) {
        int s = c % STAGES;
        CP_WAIT1();                 // chunk c resident (c+1 still in flight)
        __syncthreads();            // WAR: all warps done reading stage (c+2)%3
        if (c + 2 < NCHUNK) load_chunk(c + 2, (c + 2) % STAGES);
        CP_COMMIT();
        uint32_t st = tiles + s * STAGEB;
#pragma unroll
        for (int ks = 0; ks < 4; ks++) {
            int seg0 = ks * 2;
            uint32_t bH[4][2];
#pragma unroll
            for (int p = 0; p < 2; p++) {
                int row = n_off + p * 16 + rowoff_b;
                int seg = seg0 + segoff_b;
                uint32_t bd = st + TILEB + SWZ128(row, seg);
                uint32_t r[4];
                LDSM_X4(r, bd);
                bH[2 * p][0] = r[0]; bH[2 * p][1] = r[1];
                bH[2 * p + 1][0] = r[2]; bH[2 * p + 1][1] = r[3];
            }
#pragma unroll
            for (int mt = 0; mt < 4; mt++) {
                int row = m_off + mt * 16 + rowoff_a;
                int seg = seg0 + segoff_a;
                uint32_t ad = st + SWZ128(row, seg);
                uint32_t aH[4];
                LDSM_X4(aH, ad);
#pragma unroll
                for (int nt = 0; nt < 4; nt++)
                    MMA_FP16(acc[mt][nt], aH, bH[nt]);
            }
        }
    }

    // ---- epilogue ----
    const int colb = bx * 128;
#pragma unroll
    for (int mt = 0; mt < 4; mt++) {
        size_t slot0 = rowA0 + m_off + mt * 16 + (lane >> 2);
        size_t slot1 = slot0 + 8;
        int tok0 = 0, tok1 = 0;
        float gt0 = 0.f, gt1 = 0.f;
        if (phase2) {
            tok0 = g_tok[slot0];
            tok1 = g_tok[slot1];
            gt0 = (tok0 >= 0) ? g_gate[tok0] : 0.f;
            gt1 = (tok1 >= 0) ? g_gate[tok1] : 0.f;
        }
#pragma unroll
        for (int nt = 0; nt < 4; nt++) {
            int cl = n_off + nt * 8 + 2 * (lane & 3);
            float b0 = sb[cl], b1v = sb[cl + 1];
            float v00 = acc[mt][nt][0] + b0, v01 = acc[mt][nt][1] + b1v;
            float v10 = acc[mt][nt][2] + b0, v11 = acc[mt][nt][3] + b1v;
            if (!phase2) {
                v00 = fmaxf(v00, 0.f); v01 = fmaxf(v01, 0.f);
                v10 = fmaxf(v10, 0.f); v11 = fmaxf(v11, 0.f);
                *reinterpret_cast<uint32_t*>(g_Hh + slot0 * DIM + colb + cl) =
                    pk(__float2half_rn(v00), __float2half_rn(v01));
                *reinterpret_cast<uint32_t*>(g_Hh + slot1 * DIM + colb + cl) =
                    pk(__float2half_rn(v10), __float2half_rn(v11));
            } else {
                if (tok0 >= 0)
                    *reinterpret_cast<float2*>(out + (size_t)tok0 * DIM + colb + cl) =
                        make_float2(gt0 * v00, gt0 * v01);
                if (tok1 >= 0)
                    *reinterpret_cast<float2*>(out + (size_t)tok1 * DIM + colb + cl) =
                        make_float2(gt1 * v10, gt1 * v11);
            }
        }
    }

    if (!phase2) {
        __threadfence();            // g_Hh stores visible before counter bump
        __syncthreads();            // all threads' stores issued
        if (tid == 0) atomicAdd(&g_done[ex], 1);
    }
}

// ---------------- launch -------------------------------------------------------
extern "C" void kernel_launch(void* const* d_in, const int* in_sizes, int n_in,
                              void* d_out, int out_size) {
    const float* x  = (const float*)d_in[0];
    const float* Wr = (const float*)d_in[1];
    const float* br = (const float*)d_in[2];
    const float* W1 = (const float*)d_in[3];
    const float* b1 = (const float*)d_in[4];
    const float* W2 = (const float*)d_in[5];
    const float* b2 = (const float*)d_in[6];
    float* out = (float*)d_out;

    void *pB1h, *pB2h;
    cudaGetSymbolAddress(&pB1h, g_B1h);
    cudaGetSymbolAddress(&pB2h, g_B2h);

    cudaFuncSetAttribute(gemm_fused, cudaFuncAttributeMaxDynamicSharedMemorySize, GEMM_SMEM);

    // single side stream + 2 events (round-8 layout: verified delta=0)
    static cudaStream_t s_side = nullptr;
    static cudaEvent_t  ev_root = nullptr, ev_wt = nullptr;
    if (s_side == nullptr) {
        cudaStreamCreateWithFlags(&s_side, cudaStreamNonBlocking);
        cudaEventCreateWithFlags(&ev_root, cudaEventDisableTiming);
        cudaEventCreateWithFlags(&ev_wt,   cudaEventDisableTiming);
    }

    // fork: weight conversion runs concurrently with router/scan/dispatch
    cudaEventRecord(ev_root, 0);
    cudaStreamWaitEvent(s_side, ev_root, 0);
    dim3 wtg(16, 16, NEXP);
    wt_kernel<<<wtg, 256, 0, s_side>>>(W1, (__half*)pB1h);
    wt_kernel<<<wtg, 256, 0, s_side>>>(W2, (__half*)pB2h);
    cudaEventRecord(ev_wt, s_side);

    // main chain
    router_kernel<<<N_TOK * 32 / 256, 256>>>(x, Wr, br);
    scan_kernel<<<SCAN_BLOCKS, 1024>>>();
    dispatch_kernel<<<2 * NEXP * CAP, 256>>>(x, out);

    // join: GEMMs need converted weights
    cudaStreamWaitEvent(0, ev_wt, 0);

    gemm_fused<<<2 * G1_BLOCKS, 256, GEMM_SMEM>>>(
        (const __half*)pB1h, b1, (const __half*)pB2h, b2, out);
}